// round 14
// baseline (speedup 1.0000x reference)
#include <cuda_runtime.h>
#include <cuda_bf16.h>
#include <cuda_fp16.h>
#include <cstdint>

#define NROWS 131072
#define H 128
#define NK 20
#define NSEG 8192
#define KIN 384          // GEMM K: [emb(128) | pool(128) | h(128)]
#define GD 512           // 4*H gates
#define STEPS 11
#define SROWS 8

// ------------------- persistent state (device globals; no allocs) -------------------
__device__ float    g_h     [(size_t)NROWS * H];       // init path only
__device__ float    g_c     [(size_t)NROWS * H];
__device__ float    g_rel   [(size_t)NROWS * 2];
__device__ float    g_pos   [(size_t)NROWS * 2];
__device__ float    g_alpha [(size_t)NROWS * NK];
__device__ float    g_fd    [(size_t)NROWS * NK * 2];
__device__ unsigned g_segmax[(size_t)NSEG * H];
__device__ int      g_segstart[NSEG + 1];              // CSR bounds of sorted seg_ids
__device__ __half   g_xa    [(size_t)NROWS * KIN];     // A fp16 [n][emb|pool|h]
__device__ __half   g_Wb    [(size_t)GD * KIN];        // B fp16, gate-permuted rows
__device__ float    g_bl    [GD];                      // bias, gate-permuted
__device__ unsigned char g_mask[NROWS];
__device__ int      g_fmt;

// ------------------- low-level helpers -------------------
__device__ __forceinline__ void cp16(uint32_t dst, const void* src) {
    asm volatile("cp.async.cg.shared.global [%0], [%1], 16;" :: "r"(dst), "l"(src));
}
#define CP_COMMIT() asm volatile("cp.async.commit_group;" ::: "memory")
#define CP_WAIT(n)  asm volatile("cp.async.wait_group %0;" :: "n"(n) : "memory")

__device__ __forceinline__ void ldm4(uint32_t* r, uint32_t addr) {
    asm volatile("ldmatrix.sync.aligned.m8n8.x4.shared.b16 {%0,%1,%2,%3}, [%4];"
                 : "=r"(r[0]), "=r"(r[1]), "=r"(r[2]), "=r"(r[3]) : "r"(addr));
}
__device__ __forceinline__ void mma16816(float* d, const uint32_t* a, uint32_t b0, uint32_t b1) {
    asm volatile("mma.sync.aligned.m16n8k16.row.col.f32.f16.f16.f32 "
                 "{%0,%1,%2,%3}, {%4,%5,%6,%7}, {%8,%9}, {%0,%1,%2,%3};"
                 : "+f"(d[0]), "+f"(d[1]), "+f"(d[2]), "+f"(d[3])
                 : "r"(a[0]), "r"(a[1]), "r"(a[2]), "r"(a[3]), "r"(b0), "r"(b1));
}

__device__ __forceinline__ unsigned enc_f(float f) {
    unsigned u = __float_as_uint(f);
    return (u & 0x80000000u) ? ~u : (u | 0x80000000u);
}
__device__ __forceinline__ float dec_f(unsigned u) {
    return (u & 0x80000000u) ? __uint_as_float(u & 0x7FFFFFFFu) : __uint_as_float(~u);
}
__device__ __forceinline__ float sigm(float x) { return 1.0f / (1.0f + expf(-x)); }

__device__ __forceinline__ void store_a(size_t n, int col, float v) {
    g_xa[n * KIN + col] = __float2half_rn(v);
}

// ------------------- mask format detect + normalize -------------------
__global__ void k_mask_detect(const unsigned char* __restrict__ raw) {
    __shared__ int cnt;
    if (threadIdx.x == 0) cnt = 0;
    __syncthreads();
    int local = 0;
    for (int i = threadIdx.x; i < 4096; i += 256)
        if ((i & 3) && raw[i]) local++;
    atomicAdd(&cnt, local);
    __syncthreads();
    if (threadIdx.x == 0) g_fmt = (cnt == 0) ? 1 : 0;
}
__global__ void k_mask_norm(const unsigned char* __restrict__ raw) {
    int n = blockIdx.x * blockDim.x + threadIdx.x;
    if (n < NROWS)
        g_mask[n] = g_fmt ? (raw[(size_t)4 * n] != 0) : (raw[n] != 0);
}

// ------------------- init: CSR bounds of sorted seg_ids -------------------
__global__ void k_seg_bounds(const int* __restrict__ seg_ids) {
    int n = blockIdx.x * blockDim.x + threadIdx.x;
    if (n >= NROWS) return;
    int s = seg_ids[n];
    if (n == 0) {
        for (int q = 0; q <= s; q++) g_segstart[q] = 0;
    } else {
        int sp = seg_ids[n - 1];
        if (sp != s)
            for (int q = sp + 1; q <= s; q++) g_segstart[q] = n;
    }
    if (n == NROWS - 1)
        for (int q = s + 1; q <= NSEG; q++) g_segstart[q] = NROWS;
}

// ------ init: B fp16 gate-permuted. permuted col p=ct*128+gt*32+u <- orig gt*128+ct*32+u
__global__ void k_init_w(const float* __restrict__ Wx, const float* __restrict__ Wh,
                         const float* __restrict__ b_lstm) {
    int idx = blockIdx.x * blockDim.x + threadIdx.x;
    int tot = GD * KIN;
    for (int i = idx; i < tot; i += gridDim.x * blockDim.x) {
        int p = i / KIN, k = i % KIN;
        int ct = p >> 7, j = p & 127, gt = j >> 5, u = j & 31;
        int orig = gt * 128 + ct * 32 + u;
        float w = (k < 256) ? Wx[(size_t)k * GD + orig] : Wh[(size_t)(k - 256) * GD + orig];
        g_Wb[(size_t)p * KIN + k] = __float2half_rn(w);
    }
    if (idx < GD) {
        int p = idx;
        int ct = p >> 7, j = p & 127, gt = j >> 5, u = j & 31;
        g_bl[p] = b_lstm[gt * 128 + ct * 32 + u];
    }
}

// ------------------- init: per-row state + pred[0] -------------------
__global__ void k_init_state(const float* __restrict__ sf, const float* __restrict__ last_pos,
                             const float* __restrict__ a0, const float* __restrict__ fd0,
                             const float* __restrict__ W_out, const float* __restrict__ b_out,
                             float* __restrict__ pred0) {
    int n = blockIdx.x, t = threadIdx.x;
    __shared__ float r0[H], r1[H];
    __shared__ float av[NK];
    float hv = sf[(size_t)n * H + t];
    g_h[(size_t)n * H + t] = hv;
    g_c[(size_t)n * H + t] = 0.0f;
    r0[t] = hv * W_out[2 * t];
    r1[t] = hv * W_out[2 * t + 1];
    if (t < NK) av[t] = a0[(size_t)n * NK + t];
    __syncthreads();
    for (int s = 64; s > 0; s >>= 1) {
        if (t < s) { r0[t] += r0[t + s]; r1[t] += r1[t + s]; }
        __syncthreads();
    }
    if (t < 2) {
        float out = (t == 0 ? r0[0] : r1[0]) + b_out[t];
        g_rel[(size_t)n * 2 + t] = out;
        g_pos[(size_t)n * 2 + t] = last_pos[(size_t)n * 2 + t] + out;
        pred0[(size_t)n * 2 + t] = out;
    }
    if (t < NK) {
        float s = 0.0f;
        #pragma unroll
        for (int k = 0; k < NK; k++) s += av[k];
        g_alpha[(size_t)n * NK + t] = av[t] / s;
    }
    if (t < 2 * NK) g_fd[(size_t)n * 2 * NK + t] = fd0[(size_t)n * 2 * NK + t];
}

// ------------------- segment max init -------------------
__global__ void k_seg_clear() {
    int i = blockIdx.x * blockDim.x + threadIdx.x;
    if (i < NSEG * H) g_segmax[i] = 0u;
}

#define SEG_R 16
__global__ void k_segmax_init(const int* __restrict__ seg_ids) {
    int t = threadIdx.x;
    int r0 = blockIdx.x * SEG_R;
    __shared__ int sid[SEG_R];
    if (t < SEG_R) sid[t] = seg_ids[r0 + t];
    __syncthreads();
    int cur = sid[0];
    unsigned mx = 0u;
    #pragma unroll
    for (int r = 0; r < SEG_R; r++) {
        int s = sid[r];
        if (s != cur) {
            atomicMax(&g_segmax[(size_t)cur * H + t], mx);
            cur = s; mx = 0u;
        }
        unsigned key = enc_f(g_h[(size_t)(r0 + r) * H + t]);
        mx = mx > key ? mx : key;
    }
    atomicMax(&g_segmax[(size_t)cur * H + t], mx);
}

// ------------------- init path: emb + h cols of A -------------------
__global__ void k_emb_init(const float* __restrict__ W_pos, const float* __restrict__ b_pos,
                           const float* __restrict__ W_fld, const float* __restrict__ b_fld) {
    __shared__ float Wf[NK * 2 * 64];
    __shared__ float Wp[2 * 64];
    __shared__ float bp[64], bf[64];
    __shared__ float dtp[NK * 2];
    int t = threadIdx.x;
    for (int i = t; i < NK * 2 * 64; i += 128) Wf[i] = W_fld[i];
    if (t < 128) Wp[t] = W_pos[t];
    if (t < 64)  { bp[t] = b_pos[t]; bf[t] = b_fld[t]; }
    int base = blockIdx.x * SROWS;
    for (int r = 0; r < SROWS; r++) {
        int n = base + r;
        __syncthreads();
        if (t < 2 * NK) dtp[t] = g_alpha[(size_t)n * NK + (t >> 1)] * g_fd[(size_t)n * 2 * NK + t];
        __syncthreads();
        float rx = g_rel[(size_t)n * 2 + 0];
        float ry = g_rel[(size_t)n * 2 + 1];
        float ev;
        if (t < 64) {
            ev = rx * Wp[t] + ry * Wp[64 + t] + bp[t];
        } else {
            int e = t - 64;
            float acc = bf[e];
            #pragma unroll
            for (int k = 0; k < 2 * NK; k++) acc += dtp[k] * Wf[k * 64 + e];
            ev = acc;
        }
        store_a((size_t)n, t, ev);
        store_a((size_t)n, 256 + t, g_h[(size_t)n * H + t]);
    }
}

// -------- per-step: pool GEMM over segments, direct scatter to g_xa + segmax reset ---
#define POOL_SEGS 32
__global__ void __launch_bounds__(256) k_pool(const float* __restrict__ W_pool,
                                              const float* __restrict__ b_pool) {
    extern __shared__ float psm[];           // [H*H] W_pool + [2*H] sv
    float* sv = psm + H * H;
    int t = threadIdx.x;
    for (int i = t; i < H * H; i += 256) psm[i] = W_pool[i];
    int s0 = blockIdx.x * POOL_SEGS;
    int half = t >> 7, col = t & 127;
    float b = b_pool[col];
    __syncthreads();
    for (int p = 0; p < POOL_SEGS; p += 2) {
        int s = s0 + p + half;
        sv[t] = dec_f(g_segmax[(size_t)s * H + col]);
        g_segmax[(size_t)s * H + col] = 0u;     // reset for next step's accumulation
        __syncthreads();
        float acc = b;
        #pragma unroll 8
        for (int k = 0; k < H; k++) acc += sv[half * H + k] * psm[k * H + col];
        __half pvh = __float2half_rn(fmaxf(acc, 0.0f));
        int a = g_segstart[s], e = g_segstart[s + 1];
        for (int n = a; n < e; n++)
            g_xa[(size_t)n * KIN + 128 + col] = pvh;
        __syncthreads();
    }
}

// ---- mma.sync fp16 GEMM + fused LSTM pointwise epilogue (gate-permuted B) -----------
// CTA 128 rows x 128 permuted cols (= all 4 gates of 32 h-dims). After the mainloop,
// accs -> 32KB fp16 smem tile (reusing pipeline buffers), then per-(row,hdim)
// pointwise: c/h update + masked select, writing c (fp32) and h2 (fp16 -> g_xa).
#define NKT 12
#define SPAD 40
#define GSTAGES 3
#define GEMM_SMEM (2 * GSTAGES * 128 * SPAD * 2 + 512)

__global__ void __launch_bounds__(256) k_gemm() {
    extern __shared__ __half gsm[];
    __half (*As)[128][SPAD] = (__half (*)[128][SPAD])gsm;
    __half (*Bs)[128][SPAD] = (__half (*)[128][SPAD])(gsm + GSTAGES * 128 * SPAD);
    float* s_bias = (float*)(gsm + 2 * GSTAGES * 128 * SPAD);
    __half* sgt = gsm;                         // 128x128 fp16 gates tile (reuse, 32KB)

    int t = threadIdx.x;
    int lane = t & 31, warp = t >> 5;
    int wm = warp & 3, wn = warp >> 2;
    int col0 = blockIdx.x * 128, row0 = blockIdx.y * 128;

    if (t < 128) s_bias[t] = g_bl[col0 + t];

    float acc[2][8][4];
    #pragma unroll
    for (int i = 0; i < 2; i++)
        #pragma unroll
        for (int j = 0; j < 8; j++)
            #pragma unroll
            for (int k = 0; k < 4; k++) acc[i][j][k] = 0.0f;

    int lr = t >> 2, lc = (t & 3) * 8;
    auto issue = [&](int it, int buf) {
        int col = it * 32 + lc;
        #pragma unroll
        for (int i = 0; i < 2; i++) {
            int r = lr + i * 64;
            cp16((uint32_t)__cvta_generic_to_shared(&As[buf][r][lc]),
                 &g_xa[(size_t)(row0 + r) * KIN + col]);
            cp16((uint32_t)__cvta_generic_to_shared(&Bs[buf][r][lc]),
                 &g_Wb[(size_t)(col0 + r) * KIN + col]);
        }
        CP_COMMIT();
    };

    issue(0, 0);
    issue(1, 1);
    for (int it = 0; it < NKT; it++) {
        int buf = it % GSTAGES;
        if (it == NKT - 1) CP_WAIT(0); else CP_WAIT(1);
        __syncthreads();
        if (it + 2 < NKT) issue(it + 2, (it + 2) % GSTAGES);

        #pragma unroll
        for (int kh = 0; kh < 2; kh++) {
            uint32_t af[2][4];
            #pragma unroll
            for (int mt = 0; mt < 2; mt++) {
                int r = wm * 32 + mt * 16 + (lane & 15);
                int c = kh * 16 + (lane >> 4) * 8;
                ldm4(af[mt], (uint32_t)__cvta_generic_to_shared(&As[buf][r][c]));
            }
            uint32_t bfr[4][4];
            #pragma unroll
            for (int nt = 0; nt < 4; nt++) {
                int r = wn * 64 + nt * 16 + (lane & 7) + ((lane >> 4) & 1) * 8;
                int c = kh * 16 + ((lane >> 3) & 1) * 8;
                ldm4(bfr[nt], (uint32_t)__cvta_generic_to_shared(&Bs[buf][r][c]));
            }
            #pragma unroll
            for (int mt = 0; mt < 2; mt++)
                #pragma unroll
                for (int nt = 0; nt < 4; nt++) {
                    mma16816(acc[mt][nt * 2],     af[mt], bfr[nt][0], bfr[nt][1]);
                    mma16816(acc[mt][nt * 2 + 1], af[mt], bfr[nt][2], bfr[nt][3]);
                }
        }
    }
    __syncthreads();   // all ldmatrix reads done; pipeline smem now reusable

    // dump gates (+ bias) to smem tile
    #pragma unroll
    for (int mt = 0; mt < 2; mt++) {
        int r = wm * 32 + mt * 16 + (lane >> 2);
        #pragma unroll
        for (int nt = 0; nt < 8; nt++) {
            int cl = wn * 64 + nt * 8 + (lane & 3) * 2;
            float b0 = s_bias[cl], b1 = s_bias[cl + 1];
            *(__half2*)&sgt[r * 128 + cl] =
                __floats2half2_rn(acc[mt][nt][0] + b0, acc[mt][nt][1] + b1);
            *(__half2*)&sgt[(r + 8) * 128 + cl] =
                __floats2half2_rn(acc[mt][nt][2] + b0, acc[mt][nt][3] + b1);
        }
    }
    __syncthreads();

    // fused LSTM pointwise: tile cols = [i(0:32)|f(32:64)|g(64:96)|o(96:128)] of
    // h-dims [ct*32, ct*32+32). Thread -> (rows t>>5, t>>5+8, ...; hdim t&31).
    int hd = t & 31, rr = t >> 5;
    int colg = blockIdx.x * 32 + hd;
    for (int r = rr; r < 128; r += 8) {
        int n = row0 + r;
        bool m = g_mask[n] != 0;
        float gi = __half2float(sgt[r * 128 + hd]);
        float gf = __half2float(sgt[r * 128 + 32 + hd]);
        float gg = __half2float(sgt[r * 128 + 64 + hd]);
        float go = __half2float(sgt[r * 128 + 96 + hd]);
        float c  = g_c[(size_t)n * H + colg];
        float hp = __half2float(g_xa[(size_t)n * KIN + 256 + colg]);
        float cn = sigm(gf) * c + sigm(gi) * tanhf(gg);
        float hn = sigm(go) * tanhf(cn);
        float h2 = m ? hn : hp;
        g_c[(size_t)n * H + colg] = m ? cn : c;
        g_xa[(size_t)n * KIN + 256 + colg] = __float2half_rn(h2);
    }
}

// ------- per-step: out-proj + traj + alpha/fd + emb A-write + segmax -----------------
__global__ void __launch_bounds__(128) k_step(
    const float* __restrict__ W_pos, const float* __restrict__ b_pos,
    const float* __restrict__ W_fld, const float* __restrict__ b_fld,
    const float* __restrict__ W_out, const float* __restrict__ b_out,
    const float* __restrict__ field_A, const float* __restrict__ trans,
    const int* __restrict__ seg_ids, float* __restrict__ pred)
{
    __shared__ float Wf[2 * NK * 64];
    __shared__ float Wp[128], bps[64], bfs[64];
    __shared__ float Wo[256], bo[2];
    __shared__ float tr_s[NK * NK];
    __shared__ float fA[NK * 4];
    __shared__ float red[8];
    __shared__ float al_s[NK], z_s[NK], dtp[2 * NK];
    __shared__ float rel_s[2], pos_s[2];
    __shared__ int sid[SROWS];

    int t = threadIdx.x;
    int lane = t & 31, warp = t >> 5;
    for (int i = t; i < 2 * NK * 64; i += 128) Wf[i] = W_fld[i];
    if (t < 128) Wp[t] = W_pos[t];
    if (t < 64) { bps[t] = b_pos[t]; bfs[t] = b_fld[t]; }
    for (int i = t; i < 256; i += 128) Wo[i] = W_out[i];
    if (t < 2) bo[t] = b_out[t];
    for (int i = t; i < NK * NK; i += 128) tr_s[i] = trans[i];
    if (t < NK * 4) fA[t] = field_A[t];
    int base = blockIdx.x * SROWS;
    if (t < SROWS) sid[t] = seg_ids[base + t];
    __syncthreads();

    int cur = sid[0];
    unsigned mx = 0u;

    for (int r = 0; r < SROWS; r++) {
        int n = base + r;
        bool m = g_mask[n] != 0;
        float h2 = __half2float(g_xa[(size_t)n * KIN + 256 + t]);  // updated by epilogue

        // batched segment max for next step
        int s = sid[r];
        if (s != cur) { atomicMax(&g_segmax[(size_t)cur * H + t], mx); cur = s; mx = 0u; }
        unsigned key = enc_f(h2);
        mx = mx > key ? mx : key;

        // out = h2 @ W_out (two dot-128 via warp shuffles)
        float p0 = h2 * Wo[2 * t], p1 = h2 * Wo[2 * t + 1];
        #pragma unroll
        for (int o = 16; o > 0; o >>= 1) {
            p0 += __shfl_down_sync(0xffffffffu, p0, o);
            p1 += __shfl_down_sync(0xffffffffu, p1, o);
        }
        if (lane == 0) { red[warp] = p0; red[4 + warp] = p1; }
        if (t < NK) al_s[t] = g_alpha[(size_t)n * NK + t];
        __syncthreads();

        if (t < NK) {
            float z = 0.0f;
            #pragma unroll
            for (int k2 = 0; k2 < NK; k2++) z += al_s[k2] * tr_s[k2 * NK + t];
            z_s[t] = z;
        }
        if (t < 2) {
            float out = red[4 * t] + red[4 * t + 1] + red[4 * t + 2] + red[4 * t + 3] + bo[t];
            float rel = m ? out : g_rel[(size_t)n * 2 + t];
            float p = g_pos[(size_t)n * 2 + t] + rel;
            g_rel[(size_t)n * 2 + t] = rel;
            g_pos[(size_t)n * 2 + t] = p;
            pred[(size_t)n * 2 + t] = rel;
            rel_s[t] = rel; pos_s[t] = p;
        }
        __syncthreads();

        if (t < 2 * NK) {
            int k = t >> 1, e = t & 1;
            float a2;
            if (m) {
                float mz = z_s[0];
                #pragma unroll
                for (int k2 = 1; k2 < NK; k2++) mz = fmaxf(mz, z_s[k2]);
                float ssum = 0.0f;
                #pragma unroll
                for (int k2 = 0; k2 < NK; k2++) ssum += expf(z_s[k2] - mz);
                a2 = expf(z_s[k] - mz) / ssum;
            } else {
                a2 = al_s[k];
            }
            float fdv = m ? (pos_s[0] * fA[k * 4 + e] + pos_s[1] * fA[k * 4 + 2 + e])
                          : g_fd[(size_t)n * 2 * NK + t];
            dtp[t] = fdv * a2;
            g_fd[(size_t)n * 2 * NK + t] = fdv;
            if (e == 0) g_alpha[(size_t)n * NK + k] = a2;
        }
        __syncthreads();

        float ev;
        if (t < 64) {
            ev = rel_s[0] * Wp[t] + rel_s[1] * Wp[64 + t] + bps[t];
        } else {
            int e = t - 64;
            float acc = bfs[e];
            #pragma unroll
            for (int k = 0; k < 2 * NK; k++) acc += dtp[k] * Wf[k * 64 + e];
            ev = acc;
        }
        store_a((size_t)n, t, ev);                  // A: emb cols for next step
        __syncthreads();                            // protect smem reuse next row
    }
    atomicMax(&g_segmax[(size_t)cur * H + t], mx);
}

// ------------------- launch -------------------
extern "C" void kernel_launch(void* const* d_in, const int* in_sizes, int n_in,
                              void* d_out, int out_size) {
    const float* state_final = (const float*)d_in[0];
    const float* last_pos    = (const float*)d_in[1];
    const float* alpha0      = (const float*)d_in[2];
    const float* fields_disp0= (const float*)d_in[3];
    const float* W_pos       = (const float*)d_in[4];
    const float* b_pos       = (const float*)d_in[5];
    const float* W_fld       = (const float*)d_in[6];
    const float* b_fld       = (const float*)d_in[7];
    const float* W_pool      = (const float*)d_in[8];
    const float* b_pool      = (const float*)d_in[9];
    const float* Wx          = (const float*)d_in[10];
    const float* Wh          = (const float*)d_in[11];
    const float* b_lstm      = (const float*)d_in[12];
    const float* W_out       = (const float*)d_in[13];
    const float* b_out       = (const float*)d_in[14];
    const float* field_A     = (const float*)d_in[15];
    const float* trans       = (const float*)d_in[16];
    const int*   seg_ids     = (const int*)d_in[17];
    const unsigned char* seq_mask = (const unsigned char*)d_in[18];
    float* pred = (float*)d_out;   // (12, N, 2)

    static int attr_done = 0;
    if (!attr_done) {
        cudaFuncSetAttribute(k_gemm, cudaFuncAttributeMaxDynamicSharedMemorySize, GEMM_SMEM);
        cudaFuncSetAttribute(k_pool, cudaFuncAttributeMaxDynamicSharedMemorySize,
                             (H * H + 2 * H) * (int)sizeof(float));
        attr_done = 1;
    }

    k_mask_detect<<<1, 256>>>(seq_mask);
    k_mask_norm<<<(NROWS + 255) / 256, 256>>>(seq_mask);
    k_seg_bounds<<<(NROWS + 255) / 256, 256>>>(seg_ids);
    k_init_w<<<256, 256>>>(Wx, Wh, b_lstm);
    k_init_state<<<NROWS, 128>>>(state_final, last_pos, alpha0, fields_disp0,
                                 W_out, b_out, pred);
    k_seg_clear<<<(NSEG * H + 255) / 256, 256>>>();
    k_segmax_init<<<NROWS / SEG_R, H>>>(seg_ids);
    k_emb_init<<<NROWS / SROWS, 128>>>(W_pos, b_pos, W_fld, b_fld);

    for (int step = 1; step <= STEPS; step++) {
        k_pool<<<NSEG / POOL_SEGS, 256, (H * H + 2 * H) * sizeof(float)>>>(W_pool, b_pool);
        k_gemm<<<dim3(GD / 128, NROWS / 128), 256, GEMM_SMEM>>>();
        k_step<<<NROWS / SROWS, 128>>>(W_pos, b_pos, W_fld, b_fld, W_out, b_out,
                                       field_A, trans, seg_ids,
                                       pred + (size_t)step * NROWS * 2);
    }
}

// round 15
// speedup vs baseline: 1.1416x; 1.1416x over previous
#include <cuda_runtime.h>
#include <cuda_bf16.h>
#include <cuda_fp16.h>
#include <cstdint>

#define NROWS 131072
#define H 128
#define NK 20
#define NSEG 8192
#define KIN 384          // GEMM K: [emb(128) | pool(128) | h(128)]
#define GD 512           // 4*H gates
#define STEPS 11
#define SROWS 8

// ------------------- persistent state (device globals; no allocs) -------------------
__device__ float    g_h     [(size_t)NROWS * H];       // init path only
__device__ float    g_c     [(size_t)NROWS * H];
__device__ float    g_rel   [(size_t)NROWS * 2];
__device__ float    g_pos   [(size_t)NROWS * 2];
__device__ float    g_alpha [(size_t)NROWS * NK];
__device__ float    g_fd    [(size_t)NROWS * NK * 2];
__device__ unsigned g_segmax[(size_t)NSEG * H];
__device__ int      g_segstart[NSEG + 1];              // CSR bounds of sorted seg_ids
__device__ __half   g_xa    [(size_t)NROWS * KIN];     // A fp16 [n][emb|pool|h]
__device__ __half   g_Wb    [(size_t)GD * KIN];        // B fp16 [n][k] K-major
__device__ __half   g_gates [(size_t)NROWS * GD];      // gates fp16
__device__ float    g_bl    [GD];
__device__ unsigned char g_mask[NROWS];
__device__ int      g_fmt;

// ------------------- low-level helpers -------------------
__device__ __forceinline__ void cp16(uint32_t dst, const void* src) {
    asm volatile("cp.async.cg.shared.global [%0], [%1], 16;" :: "r"(dst), "l"(src));
}
#define CP_COMMIT() asm volatile("cp.async.commit_group;" ::: "memory")
#define CP_WAIT(n)  asm volatile("cp.async.wait_group %0;" :: "n"(n) : "memory")

__device__ __forceinline__ void ldm4(uint32_t* r, uint32_t addr) {
    asm volatile("ldmatrix.sync.aligned.m8n8.x4.shared.b16 {%0,%1,%2,%3}, [%4];"
                 : "=r"(r[0]), "=r"(r[1]), "=r"(r[2]), "=r"(r[3]) : "r"(addr));
}
__device__ __forceinline__ void mma16816(float* d, const uint32_t* a, uint32_t b0, uint32_t b1) {
    asm volatile("mma.sync.aligned.m16n8k16.row.col.f32.f16.f16.f32 "
                 "{%0,%1,%2,%3}, {%4,%5,%6,%7}, {%8,%9}, {%0,%1,%2,%3};"
                 : "+f"(d[0]), "+f"(d[1]), "+f"(d[2]), "+f"(d[3])
                 : "r"(a[0]), "r"(a[1]), "r"(a[2]), "r"(a[3]), "r"(b0), "r"(b1));
}

__device__ __forceinline__ unsigned enc_f(float f) {
    unsigned u = __float_as_uint(f);
    return (u & 0x80000000u) ? ~u : (u | 0x80000000u);
}
__device__ __forceinline__ float dec_f(unsigned u) {
    return (u & 0x80000000u) ? __uint_as_float(u & 0x7FFFFFFFu) : __uint_as_float(~u);
}
__device__ __forceinline__ float sigm(float x) { return 1.0f / (1.0f + expf(-x)); }

__device__ __forceinline__ void store_a(size_t n, int col, float v) {
    g_xa[n * KIN + col] = __float2half_rn(v);
}

__device__ __forceinline__ float warp_sum(float v) {
    #pragma unroll
    for (int o = 16; o > 0; o >>= 1) v += __shfl_xor_sync(0xffffffffu, v, o);
    return v;
}
__device__ __forceinline__ float warp_max(float v) {
    #pragma unroll
    for (int o = 16; o > 0; o >>= 1) v = fmaxf(v, __shfl_xor_sync(0xffffffffu, v, o));
    return v;
}

// ------------------- mask format detect + normalize -------------------
__global__ void k_mask_detect(const unsigned char* __restrict__ raw) {
    __shared__ int cnt;
    if (threadIdx.x == 0) cnt = 0;
    __syncthreads();
    int local = 0;
    for (int i = threadIdx.x; i < 4096; i += 256)
        if ((i & 3) && raw[i]) local++;
    atomicAdd(&cnt, local);
    __syncthreads();
    if (threadIdx.x == 0) g_fmt = (cnt == 0) ? 1 : 0;
}
__global__ void k_mask_norm(const unsigned char* __restrict__ raw) {
    int n = blockIdx.x * blockDim.x + threadIdx.x;
    if (n < NROWS)
        g_mask[n] = g_fmt ? (raw[(size_t)4 * n] != 0) : (raw[n] != 0);
}

// ------------------- init: CSR bounds of sorted seg_ids -------------------
__global__ void k_seg_bounds(const int* __restrict__ seg_ids) {
    int n = blockIdx.x * blockDim.x + threadIdx.x;
    if (n >= NROWS) return;
    int s = seg_ids[n];
    if (n == 0) {
        for (int q = 0; q <= s; q++) g_segstart[q] = 0;
    } else {
        int sp = seg_ids[n - 1];
        if (sp != s)
            for (int q = sp + 1; q <= s; q++) g_segstart[q] = n;
    }
    if (n == NROWS - 1)
        for (int q = s + 1; q <= NSEG; q++) g_segstart[q] = NROWS;
}

// ------------------- init: B fp16 [512 x 384] K-major + bias -------------------
__global__ void k_init_w(const float* __restrict__ Wx, const float* __restrict__ Wh,
                         const float* __restrict__ b_lstm) {
    int idx = blockIdx.x * blockDim.x + threadIdx.x;
    int tot = GD * KIN;
    for (int i = idx; i < tot; i += gridDim.x * blockDim.x) {
        int n = i / KIN, k = i % KIN;
        float w = (k < 256) ? Wx[(size_t)k * GD + n] : Wh[(size_t)(k - 256) * GD + n];
        g_Wb[(size_t)n * KIN + k] = __float2half_rn(w);
    }
    if (idx < GD) g_bl[idx] = b_lstm[idx];
}

// ------------------- init: per-row state + pred[0] -------------------
__global__ void k_init_state(const float* __restrict__ sf, const float* __restrict__ last_pos,
                             const float* __restrict__ a0, const float* __restrict__ fd0,
                             const float* __restrict__ W_out, const float* __restrict__ b_out,
                             float* __restrict__ pred0) {
    int n = blockIdx.x, t = threadIdx.x;
    __shared__ float r0[H], r1[H];
    __shared__ float av[NK];
    float hv = sf[(size_t)n * H + t];
    g_h[(size_t)n * H + t] = hv;
    g_c[(size_t)n * H + t] = 0.0f;
    r0[t] = hv * W_out[2 * t];
    r1[t] = hv * W_out[2 * t + 1];
    if (t < NK) av[t] = a0[(size_t)n * NK + t];
    __syncthreads();
    for (int s = 64; s > 0; s >>= 1) {
        if (t < s) { r0[t] += r0[t + s]; r1[t] += r1[t + s]; }
        __syncthreads();
    }
    if (t < 2) {
        float out = (t == 0 ? r0[0] : r1[0]) + b_out[t];
        g_rel[(size_t)n * 2 + t] = out;
        g_pos[(size_t)n * 2 + t] = last_pos[(size_t)n * 2 + t] + out;
        pred0[(size_t)n * 2 + t] = out;
    }
    if (t < NK) {
        float s = 0.0f;
        #pragma unroll
        for (int k = 0; k < NK; k++) s += av[k];
        g_alpha[(size_t)n * NK + t] = av[t] / s;
    }
    if (t < 2 * NK) g_fd[(size_t)n * 2 * NK + t] = fd0[(size_t)n * 2 * NK + t];
}

// ------------------- segment max init -------------------
__global__ void k_seg_clear() {
    int i = blockIdx.x * blockDim.x + threadIdx.x;
    if (i < NSEG * H) g_segmax[i] = 0u;
}

#define SEG_R 16
__global__ void k_segmax_init(const int* __restrict__ seg_ids) {
    int t = threadIdx.x;
    int r0 = blockIdx.x * SEG_R;
    __shared__ int sid[SEG_R];
    if (t < SEG_R) sid[t] = seg_ids[r0 + t];
    __syncthreads();
    int cur = sid[0];
    unsigned mx = 0u;
    #pragma unroll
    for (int r = 0; r < SEG_R; r++) {
        int s = sid[r];
        if (s != cur) {
            atomicMax(&g_segmax[(size_t)cur * H + t], mx);
            cur = s; mx = 0u;
        }
        unsigned key = enc_f(g_h[(size_t)(r0 + r) * H + t]);
        mx = mx > key ? mx : key;
    }
    atomicMax(&g_segmax[(size_t)cur * H + t], mx);
}

// ------------------- init path: emb + h cols of A -------------------
__global__ void k_emb_init(const float* __restrict__ W_pos, const float* __restrict__ b_pos,
                           const float* __restrict__ W_fld, const float* __restrict__ b_fld) {
    __shared__ float Wf[NK * 2 * 64];
    __shared__ float Wp[2 * 64];
    __shared__ float bp[64], bf[64];
    __shared__ float dtp[NK * 2];
    int t = threadIdx.x;
    for (int i = t; i < NK * 2 * 64; i += 128) Wf[i] = W_fld[i];
    if (t < 128) Wp[t] = W_pos[t];
    if (t < 64)  { bp[t] = b_pos[t]; bf[t] = b_fld[t]; }
    int base = blockIdx.x * SROWS;
    for (int r = 0; r < SROWS; r++) {
        int n = base + r;
        __syncthreads();
        if (t < 2 * NK) dtp[t] = g_alpha[(size_t)n * NK + (t >> 1)] * g_fd[(size_t)n * 2 * NK + t];
        __syncthreads();
        float rx = g_rel[(size_t)n * 2 + 0];
        float ry = g_rel[(size_t)n * 2 + 1];
        float ev;
        if (t < 64) {
            ev = rx * Wp[t] + ry * Wp[64 + t] + bp[t];
        } else {
            int e = t - 64;
            float acc = bf[e];
            #pragma unroll
            for (int k = 0; k < 2 * NK; k++) acc += dtp[k] * Wf[k * 64 + e];
            ev = acc;
        }
        store_a((size_t)n, t, ev);
        store_a((size_t)n, 256 + t, g_h[(size_t)n * H + t]);
    }
}

// -------- per-step: pool GEMM over segments, direct scatter to g_xa + segmax reset ---
#define POOL_SEGS 32
__global__ void __launch_bounds__(256) k_pool(const float* __restrict__ W_pool,
                                              const float* __restrict__ b_pool) {
    extern __shared__ float psm[];           // [H*H] W_pool + [2*H] sv
    float* sv = psm + H * H;
    int t = threadIdx.x;
    for (int i = t; i < H * H; i += 256) psm[i] = W_pool[i];
    int s0 = blockIdx.x * POOL_SEGS;
    int half = t >> 7, col = t & 127;
    float b = b_pool[col];
    __syncthreads();
    for (int p = 0; p < POOL_SEGS; p += 2) {
        int s = s0 + p + half;
        sv[t] = dec_f(g_segmax[(size_t)s * H + col]);
        g_segmax[(size_t)s * H + col] = 0u;     // reset for next step's accumulation
        __syncthreads();
        float acc = b;
        #pragma unroll 8
        for (int k = 0; k < H; k++) acc += sv[half * H + k] * psm[k * H + col];
        __half pvh = __float2half_rn(fmaxf(acc, 0.0f));
        int a = g_segstart[s], e = g_segstart[s + 1];
        for (int n = a; n < e; n++)
            g_xa[(size_t)n * KIN + 128 + col] = pvh;
        __syncthreads();
    }
}

// ------------------- mma.sync fp16 GEMM: gates = A x B^T + bias ----------------------
// CTA 128x128, 8 warps (4m x 2n), BK=32, 3-stage cp.async, 12 k-tiles. fp16 gates out.
#define NKT 12
#define SPAD 40    // 32 + 8 fp16 pad: 80B row stride, conflict-free ldmatrix
#define GSTAGES 3
#define GEMM_SMEM (2 * GSTAGES * 128 * SPAD * 2 + 512)

__global__ void __launch_bounds__(256) k_gemm() {
    extern __shared__ __half gsm[];
    __half (*As)[128][SPAD] = (__half (*)[128][SPAD])gsm;
    __half (*Bs)[128][SPAD] = (__half (*)[128][SPAD])(gsm + GSTAGES * 128 * SPAD);
    float* s_bias = (float*)(gsm + 2 * GSTAGES * 128 * SPAD);

    int t = threadIdx.x;
    int lane = t & 31, warp = t >> 5;
    int wm = warp & 3, wn = warp >> 2;
    int col0 = blockIdx.x * 128, row0 = blockIdx.y * 128;

    if (t < 128) s_bias[t] = g_bl[col0 + t];

    float acc[2][8][4];
    #pragma unroll
    for (int i = 0; i < 2; i++)
        #pragma unroll
        for (int j = 0; j < 8; j++)
            #pragma unroll
            for (int k = 0; k < 4; k++) acc[i][j][k] = 0.0f;

    int lr = t >> 2, lc = (t & 3) * 8;
    auto issue = [&](int it, int buf) {
        int col = it * 32 + lc;
        #pragma unroll
        for (int i = 0; i < 2; i++) {
            int r = lr + i * 64;
            cp16((uint32_t)__cvta_generic_to_shared(&As[buf][r][lc]),
                 &g_xa[(size_t)(row0 + r) * KIN + col]);
            cp16((uint32_t)__cvta_generic_to_shared(&Bs[buf][r][lc]),
                 &g_Wb[(size_t)(col0 + r) * KIN + col]);
        }
        CP_COMMIT();
    };

    issue(0, 0);
    issue(1, 1);
    for (int it = 0; it < NKT; it++) {
        int buf = it % GSTAGES;
        if (it == NKT - 1) CP_WAIT(0); else CP_WAIT(1);   // tail-safe wait
        __syncthreads();
        if (it + 2 < NKT) issue(it + 2, (it + 2) % GSTAGES);

        #pragma unroll
        for (int kh = 0; kh < 2; kh++) {
            uint32_t af[2][4];
            #pragma unroll
            for (int mt = 0; mt < 2; mt++) {
                int r = wm * 32 + mt * 16 + (lane & 15);
                int c = kh * 16 + (lane >> 4) * 8;
                ldm4(af[mt], (uint32_t)__cvta_generic_to_shared(&As[buf][r][c]));
            }
            uint32_t bfr[4][4];
            #pragma unroll
            for (int nt = 0; nt < 4; nt++) {
                int r = wn * 64 + nt * 16 + (lane & 7) + ((lane >> 4) & 1) * 8;
                int c = kh * 16 + ((lane >> 3) & 1) * 8;
                ldm4(bfr[nt], (uint32_t)__cvta_generic_to_shared(&Bs[buf][r][c]));
            }
            #pragma unroll
            for (int mt = 0; mt < 2; mt++)
                #pragma unroll
                for (int nt = 0; nt < 4; nt++) {
                    mma16816(acc[mt][nt * 2],     af[mt], bfr[nt][0], bfr[nt][1]);
                    mma16816(acc[mt][nt * 2 + 1], af[mt], bfr[nt][2], bfr[nt][3]);
                }
        }
    }

    #pragma unroll
    for (int mt = 0; mt < 2; mt++) {
        int r = row0 + wm * 32 + mt * 16 + (lane >> 2);
        #pragma unroll
        for (int nt = 0; nt < 8; nt++) {
            int cl = wn * 64 + nt * 8 + (lane & 3) * 2;
            float b0 = s_bias[cl], b1 = s_bias[cl + 1];
            __half2 v0 = __floats2half2_rn(acc[mt][nt][0] + b0, acc[mt][nt][1] + b1);
            __half2 v1 = __floats2half2_rn(acc[mt][nt][2] + b0, acc[mt][nt][3] + b1);
            *(__half2*)&g_gates[(size_t)r * GD + col0 + cl] = v0;
            *(__half2*)&g_gates[(size_t)(r + 8) * GD + col0 + cl] = v1;
        }
    }
}

// ------- per-step, warp-centric: LSTM + out + traj + alpha/fd + A-write + segmax -----
// 256 threads = 8 warps; block owns 64 rows; each warp sequentially owns 8 rows.
// No block barriers in the row loop (warp shuffles + __syncwarp only).
__global__ void __launch_bounds__(256) k_step(
    const float* __restrict__ W_pos, const float* __restrict__ b_pos,
    const float* __restrict__ W_fld, const float* __restrict__ b_fld,
    const float* __restrict__ W_out, const float* __restrict__ b_out,
    const float* __restrict__ field_A, const float* __restrict__ trans,
    const int* __restrict__ seg_ids, float* __restrict__ pred)
{
    __shared__ float Wf[2 * NK * 64];
    __shared__ float Wp[128], bps[64], bfs[64];
    __shared__ float Wo[256], bo[2];
    __shared__ float tr_s[NK * NK];
    __shared__ float fA[NK * 4];
    __shared__ float sdtp_all[8][2 * NK];
    __shared__ int sid[64];

    int t = threadIdx.x;
    int lane = t & 31, warp = t >> 5;
    for (int i = t; i < 2 * NK * 64; i += 256) Wf[i] = W_fld[i];
    if (t < 128) Wp[t] = W_pos[t];
    if (t < 64) { bps[t] = b_pos[t]; bfs[t] = b_fld[t]; }
    if (t < 256) Wo[t] = W_out[t];
    if (t < 2) bo[t] = b_out[t];
    for (int i = t; i < NK * NK; i += 256) tr_s[i] = trans[i];
    if (t < NK * 4) fA[t] = field_A[t];
    int base = blockIdx.x * 64;
    if (t < 64) sid[t] = seg_ids[base + t];
    __syncthreads();

    float* sdtp = sdtp_all[warp];
    int rbase = warp * 8;
    int cur = sid[rbase];
    unsigned mxu[4] = {0u, 0u, 0u, 0u};
    int tri = (lane < NK) ? lane : 0;          // safe trans column index

    for (int i = 0; i < 8; i++) {
        int rloc = rbase + i;
        int n = base + rloc;
        bool m = g_mask[n] != 0;

        int s = sid[rloc];
        if (s != cur) {
            #pragma unroll
            for (int j = 0; j < 4; j++)
                atomicMax(&g_segmax[(size_t)cur * H + lane + j * 32], mxu[j]);
            cur = s; mxu[0] = mxu[1] = mxu[2] = mxu[3] = 0u;
        }

        // gates + LSTM pointwise + out-projection partials (4 h-dims per lane)
        float p0 = 0.0f, p1 = 0.0f;
        #pragma unroll
        for (int j = 0; j < 4; j++) {
            int col = lane + j * 32;
            const __half* g = &g_gates[(size_t)n * GD];
            float gi = __half2float(g[col]);
            float gf = __half2float(g[col + 128]);
            float gg = __half2float(g[col + 256]);
            float go = __half2float(g[col + 384]);
            float c  = g_c[(size_t)n * H + col];
            float hp = __half2float(g_xa[(size_t)n * KIN + 256 + col]);
            float cn = sigm(gf) * c + sigm(gi) * tanhf(gg);
            float hn = sigm(go) * tanhf(cn);
            float h2 = m ? hn : hp;
            g_c[(size_t)n * H + col] = m ? cn : c;
            g_xa[(size_t)n * KIN + 256 + col] = __float2half_rn(h2);
            unsigned key = enc_f(h2);
            mxu[j] = mxu[j] > key ? mxu[j] : key;
            p0 += h2 * Wo[2 * col];
            p1 += h2 * Wo[2 * col + 1];
        }
        p0 = warp_sum(p0);
        p1 = warp_sum(p1);
        float out0 = p0 + bo[0], out1 = p1 + bo[1];
        float rel0 = m ? out0 : g_rel[(size_t)n * 2 + 0];
        float rel1 = m ? out1 : g_rel[(size_t)n * 2 + 1];
        float np0 = g_pos[(size_t)n * 2 + 0] + rel0;
        float np1 = g_pos[(size_t)n * 2 + 1] + rel1;
        if (lane == 0) {
            *(float2*)&g_rel[(size_t)n * 2] = make_float2(rel0, rel1);
            *(float2*)&g_pos[(size_t)n * 2] = make_float2(np0, np1);
            *(float2*)&pred[(size_t)n * 2] = make_float2(rel0, rel1);
        }

        // alpha propagation (lane < NK owns one k)
        float al = (lane < NK) ? g_alpha[(size_t)n * NK + lane] : 0.0f;
        float z = 0.0f;
        #pragma unroll
        for (int k2 = 0; k2 < NK; k2++)
            z += __shfl_sync(0xffffffffu, al, k2) * tr_s[k2 * NK + tri];
        float zm = (lane < NK) ? z : -1e30f;
        float mz = warp_max(zm);
        float es = (lane < NK) ? expf(z - mz) : 0.0f;
        float ssum = warp_sum(es);
        float a2 = m ? (es / ssum) : al;

        if (lane < NK) {
            int k = lane;
            float fd0, fd1;
            if (m) {
                fd0 = np0 * fA[k * 4 + 0] + np1 * fA[k * 4 + 2];
                fd1 = np0 * fA[k * 4 + 1] + np1 * fA[k * 4 + 3];
            } else {
                fd0 = g_fd[(size_t)n * 2 * NK + 2 * k];
                fd1 = g_fd[(size_t)n * 2 * NK + 2 * k + 1];
            }
            g_fd[(size_t)n * 2 * NK + 2 * k] = fd0;
            g_fd[(size_t)n * 2 * NK + 2 * k + 1] = fd1;
            g_alpha[(size_t)n * NK + k] = a2;
            sdtp[2 * k] = fd0 * a2;
            sdtp[2 * k + 1] = fd1 * a2;
        }
        __syncwarp();

        // emb cols: pos cols lane, lane+32; fld cols 64+lane, 96+lane
        float eva = rel0 * Wp[lane] + rel1 * Wp[64 + lane] + bps[lane];
        float evb = rel0 * Wp[lane + 32] + rel1 * Wp[96 + lane] + bps[lane + 32];
        float evc = bfs[lane], evd = bfs[lane + 32];
        #pragma unroll
        for (int k = 0; k < 2 * NK; k++) {
            float d = sdtp[k];
            evc += d * Wf[k * 64 + lane];
            evd += d * Wf[k * 64 + lane + 32];
        }
        store_a((size_t)n, lane, eva);
        store_a((size_t)n, lane + 32, evb);
        store_a((size_t)n, 64 + lane, evc);
        store_a((size_t)n, 96 + lane, evd);
        __syncwarp();
    }
    #pragma unroll
    for (int j = 0; j < 4; j++)
        atomicMax(&g_segmax[(size_t)cur * H + lane + j * 32], mxu[j]);
}

// ------------------- launch -------------------
extern "C" void kernel_launch(void* const* d_in, const int* in_sizes, int n_in,
                              void* d_out, int out_size) {
    const float* state_final = (const float*)d_in[0];
    const float* last_pos    = (const float*)d_in[1];
    const float* alpha0      = (const float*)d_in[2];
    const float* fields_disp0= (const float*)d_in[3];
    const float* W_pos       = (const float*)d_in[4];
    const float* b_pos       = (const float*)d_in[5];
    const float* W_fld       = (const float*)d_in[6];
    const float* b_fld       = (const float*)d_in[7];
    const float* W_pool      = (const float*)d_in[8];
    const float* b_pool      = (const float*)d_in[9];
    const float* Wx          = (const float*)d_in[10];
    const float* Wh          = (const float*)d_in[11];
    const float* b_lstm      = (const float*)d_in[12];
    const float* W_out       = (const float*)d_in[13];
    const float* b_out       = (const float*)d_in[14];
    const float* field_A     = (const float*)d_in[15];
    const float* trans       = (const float*)d_in[16];
    const int*   seg_ids     = (const int*)d_in[17];
    const unsigned char* seq_mask = (const unsigned char*)d_in[18];
    float* pred = (float*)d_out;   // (12, N, 2)

    static int attr_done = 0;
    if (!attr_done) {
        cudaFuncSetAttribute(k_gemm, cudaFuncAttributeMaxDynamicSharedMemorySize, GEMM_SMEM);
        cudaFuncSetAttribute(k_pool, cudaFuncAttributeMaxDynamicSharedMemorySize,
                             (H * H + 2 * H) * (int)sizeof(float));
        attr_done = 1;
    }

    k_mask_detect<<<1, 256>>>(seq_mask);
    k_mask_norm<<<(NROWS + 255) / 256, 256>>>(seq_mask);
    k_seg_bounds<<<(NROWS + 255) / 256, 256>>>(seg_ids);
    k_init_w<<<256, 256>>>(Wx, Wh, b_lstm);
    k_init_state<<<NROWS, 128>>>(state_final, last_pos, alpha0, fields_disp0,
                                 W_out, b_out, pred);
    k_seg_clear<<<(NSEG * H + 255) / 256, 256>>>();
    k_segmax_init<<<NROWS / SEG_R, H>>>(seg_ids);
    k_emb_init<<<NROWS / SROWS, 128>>>(W_pos, b_pos, W_fld, b_fld);

    for (int step = 1; step <= STEPS; step++) {
        k_pool<<<NSEG / POOL_SEGS, 256, (H * H + 2 * H) * sizeof(float)>>>(W_pool, b_pool);
        k_gemm<<<dim3(GD / 128, NROWS / 128), 256, GEMM_SMEM>>>();
        k_step<<<NROWS / 64, 256>>>(W_pos, b_pos, W_fld, b_fld, W_out, b_out,
                                    field_A, trans, seg_ids,
                                    pred + (size_t)step * NROWS * 2);
    }
}

// round 16
// speedup vs baseline: 1.2095x; 1.0595x over previous
#include <cuda_runtime.h>
#include <cuda_bf16.h>
#include <cuda_fp16.h>
#include <cstdint>

#define NROWS 131072
#define H 128
#define NK 20
#define NSEG 8192
#define AW 256           // g_xa row: [emb(128) | h(128)]
#define GD 512           // 4*H gates
#define STEPS 11
#define SROWS 8

// ------------------- persistent state (device globals; no allocs) -------------------
__device__ float    g_h     [(size_t)NROWS * H];       // init path only
__device__ float    g_c     [(size_t)NROWS * H];
__device__ float    g_rel   [(size_t)NROWS * 2];
__device__ float    g_pos   [(size_t)NROWS * 2];
__device__ float    g_alpha [(size_t)NROWS * NK];
__device__ float    g_fd    [(size_t)NROWS * NK * 2];
__device__ unsigned g_segmax[(size_t)NSEG * H];
__device__ __half   g_Pp    [(size_t)NSEG * H];        // pooled per-seg vector fp16
__device__ __half   g_pg    [(size_t)NSEG * GD];       // per-seg pool gates (L2-resident)
__device__ __half   g_xa    [(size_t)NROWS * AW];      // A fp16 [n][emb|h]
__device__ __half   g_Wb    [(size_t)GD * AW];         // B fp16 [n][emb k|h k]
__device__ __half   g_Wbp   [(size_t)GD * H];          // B fp16 pool rows
__device__ __half   g_gates [(size_t)NROWS * GD];      // per-row gates fp16
__device__ float    g_bl    [GD];
__device__ unsigned char g_mask[NROWS];
__device__ int      g_fmt;

// ------------------- low-level helpers -------------------
__device__ __forceinline__ void cp16(uint32_t dst, const void* src) {
    asm volatile("cp.async.cg.shared.global [%0], [%1], 16;" :: "r"(dst), "l"(src));
}
#define CP_COMMIT() asm volatile("cp.async.commit_group;" ::: "memory")
#define CP_WAIT(n)  asm volatile("cp.async.wait_group %0;" :: "n"(n) : "memory")

__device__ __forceinline__ void ldm4(uint32_t* r, uint32_t addr) {
    asm volatile("ldmatrix.sync.aligned.m8n8.x4.shared.b16 {%0,%1,%2,%3}, [%4];"
                 : "=r"(r[0]), "=r"(r[1]), "=r"(r[2]), "=r"(r[3]) : "r"(addr));
}
__device__ __forceinline__ void mma16816(float* d, const uint32_t* a, uint32_t b0, uint32_t b1) {
    asm volatile("mma.sync.aligned.m16n8k16.row.col.f32.f16.f16.f32 "
                 "{%0,%1,%2,%3}, {%4,%5,%6,%7}, {%8,%9}, {%0,%1,%2,%3};"
                 : "+f"(d[0]), "+f"(d[1]), "+f"(d[2]), "+f"(d[3])
                 : "r"(a[0]), "r"(a[1]), "r"(a[2]), "r"(a[3]), "r"(b0), "r"(b1));
}

__device__ __forceinline__ unsigned enc_f(float f) {
    unsigned u = __float_as_uint(f);
    return (u & 0x80000000u) ? ~u : (u | 0x80000000u);
}
__device__ __forceinline__ float dec_f(unsigned u) {
    return (u & 0x80000000u) ? __uint_as_float(u & 0x7FFFFFFFu) : __uint_as_float(~u);
}
__device__ __forceinline__ float sigm(float x) { return 1.0f / (1.0f + expf(-x)); }

__device__ __forceinline__ void store_a(size_t n, int col, float v) {
    g_xa[n * AW + col] = __float2half_rn(v);
}

__device__ __forceinline__ float warp_sum(float v) {
    #pragma unroll
    for (int o = 16; o > 0; o >>= 1) v += __shfl_xor_sync(0xffffffffu, v, o);
    return v;
}
__device__ __forceinline__ float warp_max(float v) {
    #pragma unroll
    for (int o = 16; o > 0; o >>= 1) v = fmaxf(v, __shfl_xor_sync(0xffffffffu, v, o));
    return v;
}

// ------------------- mask format detect + normalize -------------------
__global__ void k_mask_detect(const unsigned char* __restrict__ raw) {
    __shared__ int cnt;
    if (threadIdx.x == 0) cnt = 0;
    __syncthreads();
    int local = 0;
    for (int i = threadIdx.x; i < 4096; i += 256)
        if ((i & 3) && raw[i]) local++;
    atomicAdd(&cnt, local);
    __syncthreads();
    if (threadIdx.x == 0) g_fmt = (cnt == 0) ? 1 : 0;
}
__global__ void k_mask_norm(const unsigned char* __restrict__ raw) {
    int n = blockIdx.x * blockDim.x + threadIdx.x;
    if (n < NROWS)
        g_mask[n] = g_fmt ? (raw[(size_t)4 * n] != 0) : (raw[n] != 0);
}

// ------------------- init: B fp16 split [emb|h] + pool rows + bias -------------------
__global__ void k_init_w(const float* __restrict__ Wx, const float* __restrict__ Wh,
                         const float* __restrict__ b_lstm) {
    int idx = blockIdx.x * blockDim.x + threadIdx.x;
    int tot = GD * AW;
    for (int i = idx; i < tot; i += gridDim.x * blockDim.x) {
        int n = i / AW, k = i % AW;
        float w = (k < 128) ? Wx[(size_t)k * GD + n] : Wh[(size_t)(k - 128) * GD + n];
        g_Wb[(size_t)n * AW + k] = __float2half_rn(w);
    }
    int tot2 = GD * H;
    for (int i = idx; i < tot2; i += gridDim.x * blockDim.x) {
        int n = i / H, k = i % H;
        g_Wbp[(size_t)n * H + k] = __float2half_rn(Wx[(size_t)(128 + k) * GD + n]);
    }
    if (idx < GD) g_bl[idx] = b_lstm[idx];
}

// ------------------- init: per-row state + pred[0] -------------------
__global__ void k_init_state(const float* __restrict__ sf, const float* __restrict__ last_pos,
                             const float* __restrict__ a0, const float* __restrict__ fd0,
                             const float* __restrict__ W_out, const float* __restrict__ b_out,
                             float* __restrict__ pred0) {
    int n = blockIdx.x, t = threadIdx.x;
    __shared__ float r0[H], r1[H];
    __shared__ float av[NK];
    float hv = sf[(size_t)n * H + t];
    g_h[(size_t)n * H + t] = hv;
    g_c[(size_t)n * H + t] = 0.0f;
    r0[t] = hv * W_out[2 * t];
    r1[t] = hv * W_out[2 * t + 1];
    if (t < NK) av[t] = a0[(size_t)n * NK + t];
    __syncthreads();
    for (int s = 64; s > 0; s >>= 1) {
        if (t < s) { r0[t] += r0[t + s]; r1[t] += r1[t + s]; }
        __syncthreads();
    }
    if (t < 2) {
        float out = (t == 0 ? r0[0] : r1[0]) + b_out[t];
        g_rel[(size_t)n * 2 + t] = out;
        g_pos[(size_t)n * 2 + t] = last_pos[(size_t)n * 2 + t] + out;
        pred0[(size_t)n * 2 + t] = out;
    }
    if (t < NK) {
        float s = 0.0f;
        #pragma unroll
        for (int k = 0; k < NK; k++) s += av[k];
        g_alpha[(size_t)n * NK + t] = av[t] / s;
    }
    if (t < 2 * NK) g_fd[(size_t)n * 2 * NK + t] = fd0[(size_t)n * 2 * NK + t];
}

// ------------------- segment max init -------------------
__global__ void k_seg_clear() {
    int i = blockIdx.x * blockDim.x + threadIdx.x;
    if (i < NSEG * H) g_segmax[i] = 0u;
}

#define SEG_R 16
__global__ void k_segmax_init(const int* __restrict__ seg_ids) {
    int t = threadIdx.x;
    int r0 = blockIdx.x * SEG_R;
    __shared__ int sid[SEG_R];
    if (t < SEG_R) sid[t] = seg_ids[r0 + t];
    __syncthreads();
    int cur = sid[0];
    unsigned mx = 0u;
    #pragma unroll
    for (int r = 0; r < SEG_R; r++) {
        int s = sid[r];
        if (s != cur) {
            atomicMax(&g_segmax[(size_t)cur * H + t], mx);
            cur = s; mx = 0u;
        }
        unsigned key = enc_f(g_h[(size_t)(r0 + r) * H + t]);
        mx = mx > key ? mx : key;
    }
    atomicMax(&g_segmax[(size_t)cur * H + t], mx);
}

// ------------------- init path: emb + h cols of A -------------------
__global__ void k_emb_init(const float* __restrict__ W_pos, const float* __restrict__ b_pos,
                           const float* __restrict__ W_fld, const float* __restrict__ b_fld) {
    __shared__ float Wf[NK * 2 * 64];
    __shared__ float Wp[2 * 64];
    __shared__ float bp[64], bf[64];
    __shared__ float dtp[NK * 2];
    int t = threadIdx.x;
    for (int i = t; i < NK * 2 * 64; i += 128) Wf[i] = W_fld[i];
    if (t < 128) Wp[t] = W_pos[t];
    if (t < 64)  { bp[t] = b_pos[t]; bf[t] = b_fld[t]; }
    int base = blockIdx.x * SROWS;
    for (int r = 0; r < SROWS; r++) {
        int n = base + r;
        __syncthreads();
        if (t < 2 * NK) dtp[t] = g_alpha[(size_t)n * NK + (t >> 1)] * g_fd[(size_t)n * 2 * NK + t];
        __syncthreads();
        float rx = g_rel[(size_t)n * 2 + 0];
        float ry = g_rel[(size_t)n * 2 + 1];
        float ev;
        if (t < 64) {
            ev = rx * Wp[t] + ry * Wp[64 + t] + bp[t];
        } else {
            int e = t - 64;
            float acc = bf[e];
            #pragma unroll
            for (int k = 0; k < 2 * NK; k++) acc += dtp[k] * Wf[k * 64 + e];
            ev = acc;
        }
        store_a((size_t)n, t, ev);
        store_a((size_t)n, 128 + t, g_h[(size_t)n * H + t]);
    }
}

// -------- per-step: pool GEMM over segments -> g_Pp fp16, + segmax reset -------------
#define POOL_SEGS 32
__global__ void __launch_bounds__(256) k_pool(const float* __restrict__ W_pool,
                                              const float* __restrict__ b_pool) {
    extern __shared__ float psm[];           // [H*H] W_pool + [2*H] sv
    float* sv = psm + H * H;
    int t = threadIdx.x;
    for (int i = t; i < H * H; i += 256) psm[i] = W_pool[i];
    int s0 = blockIdx.x * POOL_SEGS;
    int half = t >> 7, col = t & 127;
    float b = b_pool[col];
    __syncthreads();
    for (int p = 0; p < POOL_SEGS; p += 2) {
        int s = s0 + p + half;
        sv[t] = dec_f(g_segmax[(size_t)s * H + col]);
        g_segmax[(size_t)s * H + col] = 0u;     // reset for next step's accumulation
        __syncthreads();
        float acc = b;
        #pragma unroll 8
        for (int k = 0; k < H; k++) acc += sv[half * H + k] * psm[k * H + col];
        g_Pp[(size_t)s * H + col] = __float2half_rn(fmaxf(acc, 0.0f));
        __syncthreads();
    }
}

// ------------------- per-step: per-segment pool gates: g_pg = Pp @ Wbp^T -------------
// CTA 128 segs x 128 cols, K=128 (4 k-tiles). Same schedule as k_gemm.
#define SPAD 40
#define GSTAGES 3
#define GEMM_SMEM (2 * GSTAGES * 128 * SPAD * 2 + 512)

__global__ void __launch_bounds__(256) k_pgemm() {
    extern __shared__ __half gsm[];
    __half (*As)[128][SPAD] = (__half (*)[128][SPAD])gsm;
    __half (*Bs)[128][SPAD] = (__half (*)[128][SPAD])(gsm + GSTAGES * 128 * SPAD);

    int t = threadIdx.x;
    int lane = t & 31, warp = t >> 5;
    int wm = warp & 3, wn = warp >> 2;
    int col0 = blockIdx.x * 128, row0 = blockIdx.y * 128;

    float acc[2][8][4];
    #pragma unroll
    for (int i = 0; i < 2; i++)
        #pragma unroll
        for (int j = 0; j < 8; j++)
            #pragma unroll
            for (int k = 0; k < 4; k++) acc[i][j][k] = 0.0f;

    int lr = t >> 2, lc = (t & 3) * 8;
    auto issue = [&](int it, int buf) {
        int col = it * 32 + lc;
        #pragma unroll
        for (int i = 0; i < 2; i++) {
            int r = lr + i * 64;
            cp16((uint32_t)__cvta_generic_to_shared(&As[buf][r][lc]),
                 &g_Pp[(size_t)(row0 + r) * H + col]);
            cp16((uint32_t)__cvta_generic_to_shared(&Bs[buf][r][lc]),
                 &g_Wbp[(size_t)(col0 + r) * H + col]);
        }
        CP_COMMIT();
    };

    issue(0, 0);
    issue(1, 1);
    for (int it = 0; it < 4; it++) {
        int buf = it % GSTAGES;
        if (it == 3) CP_WAIT(0); else CP_WAIT(1);
        __syncthreads();
        if (it + 2 < 4) issue(it + 2, (it + 2) % GSTAGES);

        #pragma unroll
        for (int kh = 0; kh < 2; kh++) {
            uint32_t af[2][4];
            #pragma unroll
            for (int mt = 0; mt < 2; mt++) {
                int r = wm * 32 + mt * 16 + (lane & 15);
                int c = kh * 16 + (lane >> 4) * 8;
                ldm4(af[mt], (uint32_t)__cvta_generic_to_shared(&As[buf][r][c]));
            }
            uint32_t bfr[4][4];
            #pragma unroll
            for (int nt = 0; nt < 4; nt++) {
                int r = wn * 64 + nt * 16 + (lane & 7) + ((lane >> 4) & 1) * 8;
                int c = kh * 16 + ((lane >> 3) & 1) * 8;
                ldm4(bfr[nt], (uint32_t)__cvta_generic_to_shared(&Bs[buf][r][c]));
            }
            #pragma unroll
            for (int mt = 0; mt < 2; mt++)
                #pragma unroll
                for (int nt = 0; nt < 4; nt++) {
                    mma16816(acc[mt][nt * 2],     af[mt], bfr[nt][0], bfr[nt][1]);
                    mma16816(acc[mt][nt * 2 + 1], af[mt], bfr[nt][2], bfr[nt][3]);
                }
        }
    }

    #pragma unroll
    for (int mt = 0; mt < 2; mt++) {
        int r = row0 + wm * 32 + mt * 16 + (lane >> 2);
        #pragma unroll
        for (int nt = 0; nt < 8; nt++) {
            int cl = wn * 64 + nt * 8 + (lane & 3) * 2;
            *(__half2*)&g_pg[(size_t)r * GD + col0 + cl] =
                __floats2half2_rn(acc[mt][nt][0], acc[mt][nt][1]);
            *(__half2*)&g_pg[(size_t)(r + 8) * GD + col0 + cl] =
                __floats2half2_rn(acc[mt][nt][2], acc[mt][nt][3]);
        }
    }
}

// ------------------- mma.sync fp16 GEMM: gates = A[emb|h] x B^T + bias ---------------
// CTA 128x128, 8 warps (4m x 2n), BK=32, 3-stage cp.async, 8 k-tiles. fp16 gates out.
#define NKT 8

__global__ void __launch_bounds__(256) k_gemm() {
    extern __shared__ __half gsm[];
    __half (*As)[128][SPAD] = (__half (*)[128][SPAD])gsm;
    __half (*Bs)[128][SPAD] = (__half (*)[128][SPAD])(gsm + GSTAGES * 128 * SPAD);
    float* s_bias = (float*)(gsm + 2 * GSTAGES * 128 * SPAD);

    int t = threadIdx.x;
    int lane = t & 31, warp = t >> 5;
    int wm = warp & 3, wn = warp >> 2;
    int col0 = blockIdx.x * 128, row0 = blockIdx.y * 128;

    if (t < 128) s_bias[t] = g_bl[col0 + t];

    float acc[2][8][4];
    #pragma unroll
    for (int i = 0; i < 2; i++)
        #pragma unroll
        for (int j = 0; j < 8; j++)
            #pragma unroll
            for (int k = 0; k < 4; k++) acc[i][j][k] = 0.0f;

    int lr = t >> 2, lc = (t & 3) * 8;
    auto issue = [&](int it, int buf) {
        int col = it * 32 + lc;
        #pragma unroll
        for (int i = 0; i < 2; i++) {
            int r = lr + i * 64;
            cp16((uint32_t)__cvta_generic_to_shared(&As[buf][r][lc]),
                 &g_xa[(size_t)(row0 + r) * AW + col]);
            cp16((uint32_t)__cvta_generic_to_shared(&Bs[buf][r][lc]),
                 &g_Wb[(size_t)(col0 + r) * AW + col]);
        }
        CP_COMMIT();
    };

    issue(0, 0);
    issue(1, 1);
    for (int it = 0; it < NKT; it++) {
        int buf = it % GSTAGES;
        if (it == NKT - 1) CP_WAIT(0); else CP_WAIT(1);   // tail-safe wait
        __syncthreads();
        if (it + 2 < NKT) issue(it + 2, (it + 2) % GSTAGES);

        #pragma unroll
        for (int kh = 0; kh < 2; kh++) {
            uint32_t af[2][4];
            #pragma unroll
            for (int mt = 0; mt < 2; mt++) {
                int r = wm * 32 + mt * 16 + (lane & 15);
                int c = kh * 16 + (lane >> 4) * 8;
                ldm4(af[mt], (uint32_t)__cvta_generic_to_shared(&As[buf][r][c]));
            }
            uint32_t bfr[4][4];
            #pragma unroll
            for (int nt = 0; nt < 4; nt++) {
                int r = wn * 64 + nt * 16 + (lane & 7) + ((lane >> 4) & 1) * 8;
                int c = kh * 16 + ((lane >> 3) & 1) * 8;
                ldm4(bfr[nt], (uint32_t)__cvta_generic_to_shared(&Bs[buf][r][c]));
            }
            #pragma unroll
            for (int mt = 0; mt < 2; mt++)
                #pragma unroll
                for (int nt = 0; nt < 4; nt++) {
                    mma16816(acc[mt][nt * 2],     af[mt], bfr[nt][0], bfr[nt][1]);
                    mma16816(acc[mt][nt * 2 + 1], af[mt], bfr[nt][2], bfr[nt][3]);
                }
        }
    }

    #pragma unroll
    for (int mt = 0; mt < 2; mt++) {
        int r = row0 + wm * 32 + mt * 16 + (lane >> 2);
        #pragma unroll
        for (int nt = 0; nt < 8; nt++) {
            int cl = wn * 64 + nt * 8 + (lane & 3) * 2;
            float b0 = s_bias[cl], b1 = s_bias[cl + 1];
            __half2 v0 = __floats2half2_rn(acc[mt][nt][0] + b0, acc[mt][nt][1] + b1);
            __half2 v1 = __floats2half2_rn(acc[mt][nt][2] + b0, acc[mt][nt][3] + b1);
            *(__half2*)&g_gates[(size_t)r * GD + col0 + cl] = v0;
            *(__half2*)&g_gates[(size_t)(r + 8) * GD + col0 + cl] = v1;
        }
    }
}

// ------- per-step, warp-centric: LSTM + out + traj + alpha/fd + A-write + segmax -----
// 256 threads = 8 warps; block owns 64 rows; each warp sequentially owns 8 rows.
// gates_total = g_gates[n] + g_pg[seg[n]] (pool part gathered from L2).
__global__ void __launch_bounds__(256) k_step(
    const float* __restrict__ W_pos, const float* __restrict__ b_pos,
    const float* __restrict__ W_fld, const float* __restrict__ b_fld,
    const float* __restrict__ W_out, const float* __restrict__ b_out,
    const float* __restrict__ field_A, const float* __restrict__ trans,
    const int* __restrict__ seg_ids, float* __restrict__ pred)
{
    __shared__ float Wf[2 * NK * 64];
    __shared__ float Wp[128], bps[64], bfs[64];
    __shared__ float Wo[256], bo[2];
    __shared__ float tr_s[NK * NK];
    __shared__ float fA[NK * 4];
    __shared__ float sdtp_all[8][2 * NK];
    __shared__ int sid[64];

    int t = threadIdx.x;
    int lane = t & 31, warp = t >> 5;
    for (int i = t; i < 2 * NK * 64; i += 256) Wf[i] = W_fld[i];
    if (t < 128) Wp[t] = W_pos[t];
    if (t < 64) { bps[t] = b_pos[t]; bfs[t] = b_fld[t]; }
    if (t < 256) Wo[t] = W_out[t];
    if (t < 2) bo[t] = b_out[t];
    for (int i = t; i < NK * NK; i += 256) tr_s[i] = trans[i];
    if (t < NK * 4) fA[t] = field_A[t];
    int base = blockIdx.x * 64;
    if (t < 64) sid[t] = seg_ids[base + t];
    __syncthreads();

    float* sdtp = sdtp_all[warp];
    int rbase = warp * 8;
    int cur = sid[rbase];
    unsigned mxu[4] = {0u, 0u, 0u, 0u};
    int tri = (lane < NK) ? lane : 0;

    for (int i = 0; i < 8; i++) {
        int rloc = rbase + i;
        int n = base + rloc;
        bool m = g_mask[n] != 0;

        int s = sid[rloc];
        if (s != cur) {
            #pragma unroll
            for (int j = 0; j < 4; j++)
                atomicMax(&g_segmax[(size_t)cur * H + lane + j * 32], mxu[j]);
            cur = s; mxu[0] = mxu[1] = mxu[2] = mxu[3] = 0u;
        }
        const __half* pg = &g_pg[(size_t)s * GD];

        float p0 = 0.0f, p1 = 0.0f;
        #pragma unroll
        for (int j = 0; j < 4; j++) {
            int col = lane + j * 32;
            const __half* g = &g_gates[(size_t)n * GD];
            float gi = __half2float(g[col])       + __half2float(pg[col]);
            float gf = __half2float(g[col + 128]) + __half2float(pg[col + 128]);
            float gg = __half2float(g[col + 256]) + __half2float(pg[col + 256]);
            float go = __half2float(g[col + 384]) + __half2float(pg[col + 384]);
            float c  = g_c[(size_t)n * H + col];
            float hp = __half2float(g_xa[(size_t)n * AW + 128 + col]);
            float cn = sigm(gf) * c + sigm(gi) * tanhf(gg);
            float hn = sigm(go) * tanhf(cn);
            float h2 = m ? hn : hp;
            g_c[(size_t)n * H + col] = m ? cn : c;
            g_xa[(size_t)n * AW + 128 + col] = __float2half_rn(h2);
            unsigned key = enc_f(h2);
            mxu[j] = mxu[j] > key ? mxu[j] : key;
            p0 += h2 * Wo[2 * col];
            p1 += h2 * Wo[2 * col + 1];
        }
        p0 = warp_sum(p0);
        p1 = warp_sum(p1);
        float out0 = p0 + bo[0], out1 = p1 + bo[1];
        float rel0 = m ? out0 : g_rel[(size_t)n * 2 + 0];
        float rel1 = m ? out1 : g_rel[(size_t)n * 2 + 1];
        float np0 = g_pos[(size_t)n * 2 + 0] + rel0;
        float np1 = g_pos[(size_t)n * 2 + 1] + rel1;
        if (lane == 0) {
            *(float2*)&g_rel[(size_t)n * 2] = make_float2(rel0, rel1);
            *(float2*)&g_pos[(size_t)n * 2] = make_float2(np0, np1);
            *(float2*)&pred[(size_t)n * 2] = make_float2(rel0, rel1);
        }

        float al = (lane < NK) ? g_alpha[(size_t)n * NK + lane] : 0.0f;
        float z = 0.0f;
        #pragma unroll
        for (int k2 = 0; k2 < NK; k2++)
            z += __shfl_sync(0xffffffffu, al, k2) * tr_s[k2 * NK + tri];
        float zm = (lane < NK) ? z : -1e30f;
        float mz = warp_max(zm);
        float es = (lane < NK) ? expf(z - mz) : 0.0f;
        float ssum = warp_sum(es);
        float a2 = m ? (es / ssum) : al;

        if (lane < NK) {
            int k = lane;
            float fd0, fd1;
            if (m) {
                fd0 = np0 * fA[k * 4 + 0] + np1 * fA[k * 4 + 2];
                fd1 = np0 * fA[k * 4 + 1] + np1 * fA[k * 4 + 3];
            } else {
                fd0 = g_fd[(size_t)n * 2 * NK + 2 * k];
                fd1 = g_fd[(size_t)n * 2 * NK + 2 * k + 1];
            }
            g_fd[(size_t)n * 2 * NK + 2 * k] = fd0;
            g_fd[(size_t)n * 2 * NK + 2 * k + 1] = fd1;
            g_alpha[(size_t)n * NK + k] = a2;
            sdtp[2 * k] = fd0 * a2;
            sdtp[2 * k + 1] = fd1 * a2;
        }
        __syncwarp();

        float eva = rel0 * Wp[lane] + rel1 * Wp[64 + lane] + bps[lane];
        float evb = rel0 * Wp[lane + 32] + rel1 * Wp[96 + lane] + bps[lane + 32];
        float evc = bfs[lane], evd = bfs[lane + 32];
        #pragma unroll
        for (int k = 0; k < 2 * NK; k++) {
            float d = sdtp[k];
            evc += d * Wf[k * 64 + lane];
            evd += d * Wf[k * 64 + lane + 32];
        }
        store_a((size_t)n, lane, eva);
        store_a((size_t)n, lane + 32, evb);
        store_a((size_t)n, 64 + lane, evc);
        store_a((size_t)n, 96 + lane, evd);
        __syncwarp();
    }
    #pragma unroll
    for (int j = 0; j < 4; j++)
        atomicMax(&g_segmax[(size_t)cur * H + lane + j * 32], mxu[j]);
}

// ------------------- launch -------------------
extern "C" void kernel_launch(void* const* d_in, const int* in_sizes, int n_in,
                              void* d_out, int out_size) {
    const float* state_final = (const float*)d_in[0];
    const float* last_pos    = (const float*)d_in[1];
    const float* alpha0      = (const float*)d_in[2];
    const float* fields_disp0= (const float*)d_in[3];
    const float* W_pos       = (const float*)d_in[4];
    const float* b_pos       = (const float*)d_in[5];
    const float* W_fld       = (const float*)d_in[6];
    const float* b_fld       = (const float*)d_in[7];
    const float* W_pool      = (const float*)d_in[8];
    const float* b_pool      = (const float*)d_in[9];
    const float* Wx          = (const float*)d_in[10];
    const float* Wh          = (const float*)d_in[11];
    const float* b_lstm      = (const float*)d_in[12];
    const float* W_out       = (const float*)d_in[13];
    const float* b_out       = (const float*)d_in[14];
    const float* field_A     = (const float*)d_in[15];
    const float* trans       = (const float*)d_in[16];
    const int*   seg_ids     = (const int*)d_in[17];
    const unsigned char* seq_mask = (const unsigned char*)d_in[18];
    float* pred = (float*)d_out;   // (12, N, 2)

    static int attr_done = 0;
    if (!attr_done) {
        cudaFuncSetAttribute(k_gemm, cudaFuncAttributeMaxDynamicSharedMemorySize, GEMM_SMEM);
        cudaFuncSetAttribute(k_pgemm, cudaFuncAttributeMaxDynamicSharedMemorySize, GEMM_SMEM);
        cudaFuncSetAttribute(k_pool, cudaFuncAttributeMaxDynamicSharedMemorySize,
                             (H * H + 2 * H) * (int)sizeof(float));
        attr_done = 1;
    }

    k_mask_detect<<<1, 256>>>(seq_mask);
    k_mask_norm<<<(NROWS + 255) / 256, 256>>>(seq_mask);
    k_init_w<<<256, 256>>>(Wx, Wh, b_lstm);
    k_init_state<<<NROWS, 128>>>(state_final, last_pos, alpha0, fields_disp0,
                                 W_out, b_out, pred);
    k_seg_clear<<<(NSEG * H + 255) / 256, 256>>>();
    k_segmax_init<<<NROWS / SEG_R, H>>>(seg_ids);
    k_emb_init<<<NROWS / SROWS, 128>>>(W_pos, b_pos, W_fld, b_fld);

    for (int step = 1; step <= STEPS; step++) {
        k_pool<<<NSEG / POOL_SEGS, 256, (H * H + 2 * H) * sizeof(float)>>>(W_pool, b_pool);
        k_pgemm<<<dim3(GD / 128, NSEG / 128), 256, GEMM_SMEM>>>();
        k_gemm<<<dim3(GD / 128, NROWS / 128), 256, GEMM_SMEM>>>();
        k_step<<<NROWS / 64, 256>>>(W_pos, b_pos, W_fld, b_fld, W_out, b_out,
                                    field_A, trans, seg_ids,
                                    pred + (size_t)step * NROWS * 2);
    }
}

// round 17
// speedup vs baseline: 1.2371x; 1.0228x over previous
#include <cuda_runtime.h>
#include <cuda_bf16.h>
#include <cuda_fp16.h>
#include <cstdint>

#define NROWS 131072
#define H 128
#define NK 20
#define NSEG 8192
#define AW 192           // A row: [rel(2) | dtp(40) | zeros(22) | h(128)]
#define GD 512           // 4*H gates
#define STEPS 11
#define SROWS 8

// ------------------- persistent state (device globals; no allocs) -------------------
__device__ float    g_h     [(size_t)NROWS * H];       // init path only
__device__ float    g_c     [(size_t)NROWS * H];
__device__ float    g_rel   [(size_t)NROWS * 2];
__device__ float    g_pos   [(size_t)NROWS * 2];
__device__ float    g_alpha [(size_t)NROWS * NK];
__device__ float    g_fd    [(size_t)NROWS * NK * 2];
__device__ unsigned g_segmax[(size_t)NSEG * H];
__device__ __half   g_Pp    [(size_t)NSEG * H];        // pooled per-seg vector fp16
__device__ __half   g_pg    [(size_t)NSEG * GD];       // per-seg pool gates (L2-resident)
__device__ __half   g_xa    [(size_t)NROWS * AW];      // A fp16 [n][rel|dtp|0|h]
__device__ __half   g_Wb    [(size_t)GD * AW];         // B fp16 [n][Wc1|Wc2|0|Wh]
__device__ __half   g_Wbp   [(size_t)GD * H];          // B fp16 pool rows
__device__ __half   g_gates [(size_t)NROWS * GD];      // per-row gates fp16
__device__ float    g_bl    [GD];                      // b_lstm + emb-bias contributions
__device__ unsigned char g_mask[NROWS];
__device__ int      g_fmt;

// ------------------- low-level helpers -------------------
__device__ __forceinline__ void cp16(uint32_t dst, const void* src) {
    asm volatile("cp.async.cg.shared.global [%0], [%1], 16;" :: "r"(dst), "l"(src));
}
#define CP_COMMIT() asm volatile("cp.async.commit_group;" ::: "memory")
#define CP_WAIT(n)  asm volatile("cp.async.wait_group %0;" :: "n"(n) : "memory")

__device__ __forceinline__ void ldm4(uint32_t* r, uint32_t addr) {
    asm volatile("ldmatrix.sync.aligned.m8n8.x4.shared.b16 {%0,%1,%2,%3}, [%4];"
                 : "=r"(r[0]), "=r"(r[1]), "=r"(r[2]), "=r"(r[3]) : "r"(addr));
}
__device__ __forceinline__ void mma16816(float* d, const uint32_t* a, uint32_t b0, uint32_t b1) {
    asm volatile("mma.sync.aligned.m16n8k16.row.col.f32.f16.f16.f32 "
                 "{%0,%1,%2,%3}, {%4,%5,%6,%7}, {%8,%9}, {%0,%1,%2,%3};"
                 : "+f"(d[0]), "+f"(d[1]), "+f"(d[2]), "+f"(d[3])
                 : "r"(a[0]), "r"(a[1]), "r"(a[2]), "r"(a[3]), "r"(b0), "r"(b1));
}

__device__ __forceinline__ unsigned enc_f(float f) {
    unsigned u = __float_as_uint(f);
    return (u & 0x80000000u) ? ~u : (u | 0x80000000u);
}
__device__ __forceinline__ float dec_f(unsigned u) {
    return (u & 0x80000000u) ? __uint_as_float(u & 0x7FFFFFFFu) : __uint_as_float(~u);
}
__device__ __forceinline__ float sigm(float x) { return 1.0f / (1.0f + expf(-x)); }

__device__ __forceinline__ void store_a(size_t n, int col, float v) {
    g_xa[n * AW + col] = __float2half_rn(v);
}

__device__ __forceinline__ float warp_sum(float v) {
    #pragma unroll
    for (int o = 16; o > 0; o >>= 1) v += __shfl_xor_sync(0xffffffffu, v, o);
    return v;
}
__device__ __forceinline__ float warp_max(float v) {
    #pragma unroll
    for (int o = 16; o > 0; o >>= 1) v = fmaxf(v, __shfl_xor_sync(0xffffffffu, v, o));
    return v;
}

// ------------------- mask format detect + normalize -------------------
__global__ void k_mask_detect(const unsigned char* __restrict__ raw) {
    __shared__ int cnt;
    if (threadIdx.x == 0) cnt = 0;
    __syncthreads();
    int local = 0;
    for (int i = threadIdx.x; i < 4096; i += 256)
        if ((i & 3) && raw[i]) local++;
    atomicAdd(&cnt, local);
    __syncthreads();
    if (threadIdx.x == 0) g_fmt = (cnt == 0) ? 1 : 0;
}
__global__ void k_mask_norm(const unsigned char* __restrict__ raw) {
    int n = blockIdx.x * blockDim.x + threadIdx.x;
    if (n < NROWS)
        g_mask[n] = g_fmt ? (raw[(size_t)4 * n] != 0) : (raw[n] != 0);
}

// ---- init: combined B. cols: [Wc1(2) | Wc2(40) | 0(22) | Wh(128)] per gate col n ----
// Wc1[r][n] = sum_j W_pos[r][j] Wx[j][n];  Wc2[d][n] = sum_j W_fld[d][j] Wx[64+j][n]
// g_bl[n] = b_lstm[n] + sum_j b_pos[j] Wx[j][n] + sum_j b_fld[j] Wx[64+j][n]
__global__ void k_init_w(const float* __restrict__ Wx, const float* __restrict__ Wh,
                         const float* __restrict__ b_lstm,
                         const float* __restrict__ W_pos, const float* __restrict__ b_pos,
                         const float* __restrict__ W_fld, const float* __restrict__ b_fld) {
    int idx = blockIdx.x * blockDim.x + threadIdx.x;
    int tot = GD * AW;
    for (int i = idx; i < tot; i += gridDim.x * blockDim.x) {
        int n = i / AW, k = i % AW;
        float w;
        if (k < 2) {
            w = 0.0f;
            for (int j = 0; j < 64; j++) w += W_pos[k * 64 + j] * Wx[(size_t)j * GD + n];
        } else if (k < 42) {
            int d = k - 2;
            w = 0.0f;
            for (int j = 0; j < 64; j++) w += W_fld[d * 64 + j] * Wx[(size_t)(64 + j) * GD + n];
        } else if (k < 64) {
            w = 0.0f;
        } else {
            w = Wh[(size_t)(k - 64) * GD + n];
        }
        g_Wb[(size_t)n * AW + k] = __float2half_rn(w);
    }
    int tot2 = GD * H;
    for (int i = idx; i < tot2; i += gridDim.x * blockDim.x) {
        int n = i / H, k = i % H;
        g_Wbp[(size_t)n * H + k] = __float2half_rn(Wx[(size_t)(128 + k) * GD + n]);
    }
    if (idx < GD) {
        float b = b_lstm[idx];
        for (int j = 0; j < 64; j++) {
            b += b_pos[j] * Wx[(size_t)j * GD + idx];
            b += b_fld[j] * Wx[(size_t)(64 + j) * GD + idx];
        }
        g_bl[idx] = b;
    }
}

// ------------------- init: per-row state + pred[0] -------------------
__global__ void k_init_state(const float* __restrict__ sf, const float* __restrict__ last_pos,
                             const float* __restrict__ a0, const float* __restrict__ fd0,
                             const float* __restrict__ W_out, const float* __restrict__ b_out,
                             float* __restrict__ pred0) {
    int n = blockIdx.x, t = threadIdx.x;
    __shared__ float r0[H], r1[H];
    __shared__ float av[NK];
    float hv = sf[(size_t)n * H + t];
    g_h[(size_t)n * H + t] = hv;
    g_c[(size_t)n * H + t] = 0.0f;
    r0[t] = hv * W_out[2 * t];
    r1[t] = hv * W_out[2 * t + 1];
    if (t < NK) av[t] = a0[(size_t)n * NK + t];
    __syncthreads();
    for (int s = 64; s > 0; s >>= 1) {
        if (t < s) { r0[t] += r0[t + s]; r1[t] += r1[t + s]; }
        __syncthreads();
    }
    if (t < 2) {
        float out = (t == 0 ? r0[0] : r1[0]) + b_out[t];
        g_rel[(size_t)n * 2 + t] = out;
        g_pos[(size_t)n * 2 + t] = last_pos[(size_t)n * 2 + t] + out;
        pred0[(size_t)n * 2 + t] = out;
    }
    if (t < NK) {
        float s = 0.0f;
        #pragma unroll
        for (int k = 0; k < NK; k++) s += av[k];
        g_alpha[(size_t)n * NK + t] = av[t] / s;
    }
    if (t < 2 * NK) g_fd[(size_t)n * 2 * NK + t] = fd0[(size_t)n * 2 * NK + t];
}

// ------------------- segment max init -------------------
__global__ void k_seg_clear() {
    int i = blockIdx.x * blockDim.x + threadIdx.x;
    if (i < NSEG * H) g_segmax[i] = 0u;
}

#define SEG_R 16
__global__ void k_segmax_init(const int* __restrict__ seg_ids) {
    int t = threadIdx.x;
    int r0 = blockIdx.x * SEG_R;
    __shared__ int sid[SEG_R];
    if (t < SEG_R) sid[t] = seg_ids[r0 + t];
    __syncthreads();
    int cur = sid[0];
    unsigned mx = 0u;
    #pragma unroll
    for (int r = 0; r < SEG_R; r++) {
        int s = sid[r];
        if (s != cur) {
            atomicMax(&g_segmax[(size_t)cur * H + t], mx);
            cur = s; mx = 0u;
        }
        unsigned key = enc_f(g_h[(size_t)(r0 + r) * H + t]);
        mx = mx > key ? mx : key;
    }
    atomicMax(&g_segmax[(size_t)cur * H + t], mx);
}

// ------------------- init path: A rows = [rel | dtp | 0 | h] -------------------
__global__ void k_emb_init() {
    int t = threadIdx.x;
    int base = blockIdx.x * SROWS;
    for (int r = 0; r < SROWS; r++) {
        int n = base + r;
        if (t < 64) {
            float v;
            if (t < 2)       v = g_rel[(size_t)n * 2 + t];
            else if (t < 42) {
                int d = t - 2;
                v = g_alpha[(size_t)n * NK + (d >> 1)] * g_fd[(size_t)n * 2 * NK + d];
            } else            v = 0.0f;
            store_a((size_t)n, t, v);
        }
        store_a((size_t)n, 64 + t, g_h[(size_t)n * H + t]);
    }
}

// -------- per-step: pool GEMM over segments -> g_Pp fp16, + segmax reset -------------
#define POOL_SEGS 32
__global__ void __launch_bounds__(256) k_pool(const float* __restrict__ W_pool,
                                              const float* __restrict__ b_pool) {
    extern __shared__ float psm[];           // [H*H] W_pool + [2*H] sv
    float* sv = psm + H * H;
    int t = threadIdx.x;
    for (int i = t; i < H * H; i += 256) psm[i] = W_pool[i];
    int s0 = blockIdx.x * POOL_SEGS;
    int half = t >> 7, col = t & 127;
    float b = b_pool[col];
    __syncthreads();
    for (int p = 0; p < POOL_SEGS; p += 2) {
        int s = s0 + p + half;
        sv[t] = dec_f(g_segmax[(size_t)s * H + col]);
        g_segmax[(size_t)s * H + col] = 0u;
        __syncthreads();
        float acc = b;
        #pragma unroll 8
        for (int k = 0; k < H; k++) acc += sv[half * H + k] * psm[k * H + col];
        g_Pp[(size_t)s * H + col] = __float2half_rn(fmaxf(acc, 0.0f));
        __syncthreads();
    }
}

// ------------------- per-step: per-segment pool gates: g_pg = Pp @ Wbp^T -------------
#define SPAD 40
#define GSTAGES 3
#define GEMM_SMEM (2 * GSTAGES * 128 * SPAD * 2 + 512)

__global__ void __launch_bounds__(256) k_pgemm() {
    extern __shared__ __half gsm[];
    __half (*As)[128][SPAD] = (__half (*)[128][SPAD])gsm;
    __half (*Bs)[128][SPAD] = (__half (*)[128][SPAD])(gsm + GSTAGES * 128 * SPAD);

    int t = threadIdx.x;
    int lane = t & 31, warp = t >> 5;
    int wm = warp & 3, wn = warp >> 2;
    int col0 = blockIdx.x * 128, row0 = blockIdx.y * 128;

    float acc[2][8][4];
    #pragma unroll
    for (int i = 0; i < 2; i++)
        #pragma unroll
        for (int j = 0; j < 8; j++)
            #pragma unroll
            for (int k = 0; k < 4; k++) acc[i][j][k] = 0.0f;

    int lr = t >> 2, lc = (t & 3) * 8;
    auto issue = [&](int it, int buf) {
        int col = it * 32 + lc;
        #pragma unroll
        for (int i = 0; i < 2; i++) {
            int r = lr + i * 64;
            cp16((uint32_t)__cvta_generic_to_shared(&As[buf][r][lc]),
                 &g_Pp[(size_t)(row0 + r) * H + col]);
            cp16((uint32_t)__cvta_generic_to_shared(&Bs[buf][r][lc]),
                 &g_Wbp[(size_t)(col0 + r) * H + col]);
        }
        CP_COMMIT();
    };

    issue(0, 0);
    issue(1, 1);
    for (int it = 0; it < 4; it++) {
        int buf = it % GSTAGES;
        if (it == 3) CP_WAIT(0); else CP_WAIT(1);
        __syncthreads();
        if (it + 2 < 4) issue(it + 2, (it + 2) % GSTAGES);

        #pragma unroll
        for (int kh = 0; kh < 2; kh++) {
            uint32_t af[2][4];
            #pragma unroll
            for (int mt = 0; mt < 2; mt++) {
                int r = wm * 32 + mt * 16 + (lane & 15);
                int c = kh * 16 + (lane >> 4) * 8;
                ldm4(af[mt], (uint32_t)__cvta_generic_to_shared(&As[buf][r][c]));
            }
            uint32_t bfr[4][4];
            #pragma unroll
            for (int nt = 0; nt < 4; nt++) {
                int r = wn * 64 + nt * 16 + (lane & 7) + ((lane >> 4) & 1) * 8;
                int c = kh * 16 + ((lane >> 3) & 1) * 8;
                ldm4(bfr[nt], (uint32_t)__cvta_generic_to_shared(&Bs[buf][r][c]));
            }
            #pragma unroll
            for (int mt = 0; mt < 2; mt++)
                #pragma unroll
                for (int nt = 0; nt < 4; nt++) {
                    mma16816(acc[mt][nt * 2],     af[mt], bfr[nt][0], bfr[nt][1]);
                    mma16816(acc[mt][nt * 2 + 1], af[mt], bfr[nt][2], bfr[nt][3]);
                }
        }
    }

    #pragma unroll
    for (int mt = 0; mt < 2; mt++) {
        int r = row0 + wm * 32 + mt * 16 + (lane >> 2);
        #pragma unroll
        for (int nt = 0; nt < 8; nt++) {
            int cl = wn * 64 + nt * 8 + (lane & 3) * 2;
            *(__half2*)&g_pg[(size_t)r * GD + col0 + cl] =
                __floats2half2_rn(acc[mt][nt][0], acc[mt][nt][1]);
            *(__half2*)&g_pg[(size_t)(r + 8) * GD + col0 + cl] =
                __floats2half2_rn(acc[mt][nt][2], acc[mt][nt][3]);
        }
    }
}

// --------------- mma.sync fp16 GEMM: gates = A[rel|dtp|0|h] x B^T + bias -------------
// CTA 128x128, 8 warps, BK=32, 3-stage cp.async, 6 k-tiles.
#define NKT 6

__global__ void __launch_bounds__(256) k_gemm() {
    extern __shared__ __half gsm[];
    __half (*As)[128][SPAD] = (__half (*)[128][SPAD])gsm;
    __half (*Bs)[128][SPAD] = (__half (*)[128][SPAD])(gsm + GSTAGES * 128 * SPAD);
    float* s_bias = (float*)(gsm + 2 * GSTAGES * 128 * SPAD);

    int t = threadIdx.x;
    int lane = t & 31, warp = t >> 5;
    int wm = warp & 3, wn = warp >> 2;
    int col0 = blockIdx.x * 128, row0 = blockIdx.y * 128;

    if (t < 128) s_bias[t] = g_bl[col0 + t];

    float acc[2][8][4];
    #pragma unroll
    for (int i = 0; i < 2; i++)
        #pragma unroll
        for (int j = 0; j < 8; j++)
            #pragma unroll
            for (int k = 0; k < 4; k++) acc[i][j][k] = 0.0f;

    int lr = t >> 2, lc = (t & 3) * 8;
    auto issue = [&](int it, int buf) {
        int col = it * 32 + lc;
        #pragma unroll
        for (int i = 0; i < 2; i++) {
            int r = lr + i * 64;
            cp16((uint32_t)__cvta_generic_to_shared(&As[buf][r][lc]),
                 &g_xa[(size_t)(row0 + r) * AW + col]);
            cp16((uint32_t)__cvta_generic_to_shared(&Bs[buf][r][lc]),
                 &g_Wb[(size_t)(col0 + r) * AW + col]);
        }
        CP_COMMIT();
    };

    issue(0, 0);
    issue(1, 1);
    for (int it = 0; it < NKT; it++) {
        int buf = it % GSTAGES;
        if (it == NKT - 1) CP_WAIT(0); else CP_WAIT(1);
        __syncthreads();
        if (it + 2 < NKT) issue(it + 2, (it + 2) % GSTAGES);

        #pragma unroll
        for (int kh = 0; kh < 2; kh++) {
            uint32_t af[2][4];
            #pragma unroll
            for (int mt = 0; mt < 2; mt++) {
                int r = wm * 32 + mt * 16 + (lane & 15);
                int c = kh * 16 + (lane >> 4) * 8;
                ldm4(af[mt], (uint32_t)__cvta_generic_to_shared(&As[buf][r][c]));
            }
            uint32_t bfr[4][4];
            #pragma unroll
            for (int nt = 0; nt < 4; nt++) {
                int r = wn * 64 + nt * 16 + (lane & 7) + ((lane >> 4) & 1) * 8;
                int c = kh * 16 + ((lane >> 3) & 1) * 8;
                ldm4(bfr[nt], (uint32_t)__cvta_generic_to_shared(&Bs[buf][r][c]));
            }
            #pragma unroll
            for (int mt = 0; mt < 2; mt++)
                #pragma unroll
                for (int nt = 0; nt < 4; nt++) {
                    mma16816(acc[mt][nt * 2],     af[mt], bfr[nt][0], bfr[nt][1]);
                    mma16816(acc[mt][nt * 2 + 1], af[mt], bfr[nt][2], bfr[nt][3]);
                }
        }
    }

    #pragma unroll
    for (int mt = 0; mt < 2; mt++) {
        int r = row0 + wm * 32 + mt * 16 + (lane >> 2);
        #pragma unroll
        for (int nt = 0; nt < 8; nt++) {
            int cl = wn * 64 + nt * 8 + (lane & 3) * 2;
            float b0 = s_bias[cl], b1 = s_bias[cl + 1];
            __half2 v0 = __floats2half2_rn(acc[mt][nt][0] + b0, acc[mt][nt][1] + b1);
            __half2 v1 = __floats2half2_rn(acc[mt][nt][2] + b0, acc[mt][nt][3] + b1);
            *(__half2*)&g_gates[(size_t)r * GD + col0 + cl] = v0;
            *(__half2*)&g_gates[(size_t)(r + 8) * GD + col0 + cl] = v1;
        }
    }
}

// ------- per-step, warp-centric: LSTM + out + traj + alpha/fd + A-write + segmax -----
// gates_total = g_gates[n] + g_pg[seg[n]]. A-writes: rel(2), dtp(40), h(128).
__global__ void __launch_bounds__(256) k_step(
    const float* __restrict__ W_out, const float* __restrict__ b_out,
    const float* __restrict__ field_A, const float* __restrict__ trans,
    const int* __restrict__ seg_ids, float* __restrict__ pred)
{
    __shared__ float Wo[256], bo[2];
    __shared__ float tr_s[NK * NK];
    __shared__ float fA[NK * 4];
    __shared__ int sid[64];

    int t = threadIdx.x;
    int lane = t & 31, warp = t >> 5;
    if (t < 256) Wo[t] = W_out[t];
    if (t < 2) bo[t] = b_out[t];
    for (int i = t; i < NK * NK; i += 256) tr_s[i] = trans[i];
    if (t < NK * 4) fA[t] = field_A[t];
    int base = blockIdx.x * 64;
    if (t < 64) sid[t] = seg_ids[base + t];
    __syncthreads();

    int rbase = warp * 8;
    int cur = sid[rbase];
    unsigned mxu[4] = {0u, 0u, 0u, 0u};
    int tri = (lane < NK) ? lane : 0;

    for (int i = 0; i < 8; i++) {
        int rloc = rbase + i;
        int n = base + rloc;
        bool m = g_mask[n] != 0;

        int s = sid[rloc];
        if (s != cur) {
            #pragma unroll
            for (int j = 0; j < 4; j++)
                atomicMax(&g_segmax[(size_t)cur * H + lane + j * 32], mxu[j]);
            cur = s; mxu[0] = mxu[1] = mxu[2] = mxu[3] = 0u;
        }
        const __half* pg = &g_pg[(size_t)s * GD];

        float p0 = 0.0f, p1 = 0.0f;
        #pragma unroll
        for (int j = 0; j < 4; j++) {
            int col = lane + j * 32;
            const __half* g = &g_gates[(size_t)n * GD];
            float gi = __half2float(g[col])       + __half2float(pg[col]);
            float gf = __half2float(g[col + 128]) + __half2float(pg[col + 128]);
            float gg = __half2float(g[col + 256]) + __half2float(pg[col + 256]);
            float go = __half2float(g[col + 384]) + __half2float(pg[col + 384]);
            float c  = g_c[(size_t)n * H + col];
            float hp = __half2float(g_xa[(size_t)n * AW + 64 + col]);
            float cn = sigm(gf) * c + sigm(gi) * tanhf(gg);
            float hn = sigm(go) * tanhf(cn);
            float h2 = m ? hn : hp;
            g_c[(size_t)n * H + col] = m ? cn : c;
            g_xa[(size_t)n * AW + 64 + col] = __float2half_rn(h2);
            unsigned key = enc_f(h2);
            mxu[j] = mxu[j] > key ? mxu[j] : key;
            p0 += h2 * Wo[2 * col];
            p1 += h2 * Wo[2 * col + 1];
        }
        p0 = warp_sum(p0);
        p1 = warp_sum(p1);
        float out0 = p0 + bo[0], out1 = p1 + bo[1];
        float rel0 = m ? out0 : g_rel[(size_t)n * 2 + 0];
        float rel1 = m ? out1 : g_rel[(size_t)n * 2 + 1];
        float np0 = g_pos[(size_t)n * 2 + 0] + rel0;
        float np1 = g_pos[(size_t)n * 2 + 1] + rel1;
        if (lane == 0) {
            *(float2*)&g_rel[(size_t)n * 2] = make_float2(rel0, rel1);
            *(float2*)&g_pos[(size_t)n * 2] = make_float2(np0, np1);
            *(float2*)&pred[(size_t)n * 2] = make_float2(rel0, rel1);
            store_a((size_t)n, 0, rel0);
            store_a((size_t)n, 1, rel1);
        }

        float al = (lane < NK) ? g_alpha[(size_t)n * NK + lane] : 0.0f;
        float z = 0.0f;
        #pragma unroll
        for (int k2 = 0; k2 < NK; k2++)
            z += __shfl_sync(0xffffffffu, al, k2) * tr_s[k2 * NK + tri];
        float zm = (lane < NK) ? z : -1e30f;
        float mz = warp_max(zm);
        float es = (lane < NK) ? expf(z - mz) : 0.0f;
        float ssum = warp_sum(es);
        float a2 = m ? (es / ssum) : al;

        if (lane < NK) {
            int k = lane;
            float fd0, fd1;
            if (m) {
                fd0 = np0 * fA[k * 4 + 0] + np1 * fA[k * 4 + 2];
                fd1 = np0 * fA[k * 4 + 1] + np1 * fA[k * 4 + 3];
            } else {
                fd0 = g_fd[(size_t)n * 2 * NK + 2 * k];
                fd1 = g_fd[(size_t)n * 2 * NK + 2 * k + 1];
            }
            g_fd[(size_t)n * 2 * NK + 2 * k] = fd0;
            g_fd[(size_t)n * 2 * NK + 2 * k + 1] = fd1;
            g_alpha[(size_t)n * NK + k] = a2;
            store_a((size_t)n, 2 + 2 * k, fd0 * a2);
            store_a((size_t)n, 3 + 2 * k, fd1 * a2);
        }
        __syncwarp();
    }
    #pragma unroll
    for (int j = 0; j < 4; j++)
        atomicMax(&g_segmax[(size_t)cur * H + lane + j * 32], mxu[j]);
}

// ------------------- launch -------------------
extern "C" void kernel_launch(void* const* d_in, const int* in_sizes, int n_in,
                              void* d_out, int out_size) {
    const float* state_final = (const float*)d_in[0];
    const float* last_pos    = (const float*)d_in[1];
    const float* alpha0      = (const float*)d_in[2];
    const float* fields_disp0= (const float*)d_in[3];
    const float* W_pos       = (const float*)d_in[4];
    const float* b_pos       = (const float*)d_in[5];
    const float* W_fld       = (const float*)d_in[6];
    const float* b_fld       = (const float*)d_in[7];
    const float* W_pool      = (const float*)d_in[8];
    const float* b_pool      = (const float*)d_in[9];
    const float* Wx          = (const float*)d_in[10];
    const float* Wh          = (const float*)d_in[11];
    const float* b_lstm      = (const float*)d_in[12];
    const float* W_out       = (const float*)d_in[13];
    const float* b_out       = (const float*)d_in[14];
    const float* field_A     = (const float*)d_in[15];
    const float* trans       = (const float*)d_in[16];
    const int*   seg_ids     = (const int*)d_in[17];
    const unsigned char* seq_mask = (const unsigned char*)d_in[18];
    float* pred = (float*)d_out;   // (12, N, 2)

    static int attr_done = 0;
    if (!attr_done) {
        cudaFuncSetAttribute(k_gemm, cudaFuncAttributeMaxDynamicSharedMemorySize, GEMM_SMEM);
        cudaFuncSetAttribute(k_pgemm, cudaFuncAttributeMaxDynamicSharedMemorySize, GEMM_SMEM);
        cudaFuncSetAttribute(k_pool, cudaFuncAttributeMaxDynamicSharedMemorySize,
                             (H * H + 2 * H) * (int)sizeof(float));
        attr_done = 1;
    }

    k_mask_detect<<<1, 256>>>(seq_mask);
    k_mask_norm<<<(NROWS + 255) / 256, 256>>>(seq_mask);
    k_init_w<<<256, 256>>>(Wx, Wh, b_lstm, W_pos, b_pos, W_fld, b_fld);
    k_init_state<<<NROWS, 128>>>(state_final, last_pos, alpha0, fields_disp0,
                                 W_out, b_out, pred);
    k_seg_clear<<<(NSEG * H + 255) / 256, 256>>>();
    k_segmax_init<<<NROWS / SEG_R, H>>>(seg_ids);
    k_emb_init<<<NROWS / SROWS, 128>>>();

    for (int step = 1; step <= STEPS; step++) {
        k_pool<<<NSEG / POOL_SEGS, 256, (H * H + 2 * H) * sizeof(float)>>>(W_pool, b_pool);
        k_pgemm<<<dim3(GD / 128, NSEG / 128), 256, GEMM_SMEM>>>();
        k_gemm<<<dim3(GD / 128, NROWS / 128), 256, GEMM_SMEM>>>();
        k_step<<<NROWS / 64, 256>>>(W_out, b_out, field_A, trans, seg_ids,
                                    pred + (size_t)step * NROWS * 2);
    }
}